// round 12
// baseline (speedup 1.0000x reference)
#include <cuda_runtime.h>
#include <cstdint>

#define N0 48000
#define N1MAX 32000
#define EPSV 1e-4f

__device__ float g_f0a[(N0 + 1) * 32];
__device__ float g_f0b[(N0 + 1) * 32];
__device__ float g_f0c[(N0 + 1) * 32];
__device__ float g_cat[(N0 + 1) * 64];
__device__ float g_f1a[(N1MAX + 1) * 64];
__device__ float g_f1b[(N1MAX + 1) * 64];
__device__ float g_f1c[(N1MAX + 1) * 64];
__device__ int g_nbr0[(N0 + 1) * 27];
__device__ int g_nbr1[(N1MAX + 1) * 27];
__device__ int g_nbrD[(N1MAX + 1) * 8];
__device__ int g_parent[N0 + 1];
__device__ int g_kid[N0 + 1];

// ---------------- tf32 helpers ----------------
__device__ __forceinline__ uint32_t tf32_of(float v) {
    uint32_t u;
    asm("cvt.rna.tf32.f32 %0, %1;" : "=r"(u) : "f"(v));
    return u;
}
__device__ __forceinline__ void mma8(float4& d, const uint32_t* a, const uint32_t* b) {
    asm volatile(
        "mma.sync.aligned.m16n8k8.row.col.f32.tf32.tf32.f32 "
        "{%0,%1,%2,%3}, {%4,%5,%6,%7}, {%8,%9}, {%0,%1,%2,%3};"
        : "+f"(d.x), "+f"(d.y), "+f"(d.z), "+f"(d.w)
        : "r"(a[0]), "r"(a[1]), "r"(a[2]), "r"(a[3]), "r"(b[0]), "r"(b[1]));
}

// ---------------- small utility kernels ----------------
__global__ void fill_i32(int* p, int count, int val, const int* vptr) {
    int t = blockIdx.x * blockDim.x + threadIdx.x;
    if (t >= count) return;
    p[t] = vptr ? *vptr : val;
}

__global__ void scatter_pairs(const int* __restrict__ pin, const int* __restrict__ pout,
                              int total, int P, int K, int* __restrict__ nbr) {
    int t = blockIdx.x * blockDim.x + threadIdx.x;
    if (t >= total) return;
    int k = t / P;
    nbr[pout[t] * K + k] = pin[t];
}

__global__ void scatter_parent(const int* __restrict__ din, const int* __restrict__ dout,
                               int total, int P, int n0,
                               int* __restrict__ parent, int* __restrict__ kid) {
    int t = blockIdx.x * blockDim.x + threadIdx.x;
    if (t >= total) return;
    int k = t / P;
    int i = din[t];
    if (i < n0) { parent[i] = dout[t]; kid[i] = k; }
}

template <int C>
__global__ void bnrelu_k(const float* __restrict__ x, const float* __restrict__ bn,
                         float* __restrict__ y, int n_host, const int* __restrict__ n_dev,
                         int total) {
    int t = blockIdx.x * blockDim.x + threadIdx.x;
    if (t >= total) return;
    int n = n_dev ? *n_dev : n_host;
    int r = t / C, c = t % C;
    float v = 0.f;
    if (r < n) {
        float g = bn[c], be = bn[C + c], m = bn[2 * C + c], va = bn[3 * C + c];
        v = fmaxf((x[t] - m) * (g * rsqrtf(va + EPSV)) + be, 0.f);
    }
    y[t] = v;
}

// ---------------- mma.sync tf32 gather implicit-GEMM sparse conv ----------
// out[r,:] = sum_k bnrelu(x[nbr[r][k],:]) @ W[k]  (+ res[r,:])
// Tile M=128 rows, 8 warps, warp owns 16 rows x COUT. 3xTF32 for precision.
template <int CIN, int COUT>
__global__ void __launch_bounds__(256)
conv_mma(const float* __restrict__ x, const float* __restrict__ bn,
         const float* __restrict__ W, const int* __restrict__ nbr, int K,
         const float* __restrict__ res, float* __restrict__ out,
         int nout_h, const int* __restrict__ nout_d,
         int nin_h, const int* __restrict__ nin_d) {
    constexpr int M = 128;
    constexpr int PX = CIN + 4;     // Xs pitch: A-frag LDS bank = (4r+c)%32, conflict-free
    constexpr int PW = COUT + 4;    // W pitch: float4-storable, 2-way LDS conflicts max
    constexpr int NT = 256;
    constexpr int KS = CIN / 8;
    constexpr int NTILE = COUT / 8;
    extern __shared__ float smem[];
    float* Xs  = smem;                                  // M * PX
    float* Whi = Xs + M * PX;                           // CIN * PW (tf32 bits)
    float* Wlo = Whi + CIN * PW;                        // CIN * PW (tf32 bits)
    unsigned short* idxAll = (unsigned short*)(Wlo + CIN * PW);  // M*K
    float* sc = (float*)(idxAll + M * K);               // CIN
    float* bi = sc + CIN;

    int n = nout_d ? *nout_d : nout_h;
    int nin = nin_d ? *nin_d : nin_h;
    int row0 = blockIdx.x * M;
    if (row0 >= n) return;
    int tid = threadIdx.x, wid = tid >> 5, lane = tid & 31;
    int grp = lane >> 2, tg = lane & 3;

    if (tid < CIN) {
        float g = bn[tid], be = bn[CIN + tid], m = bn[2 * CIN + tid], va = bn[3 * CIN + tid];
        float s = g * rsqrtf(va + EPSV);
        sc[tid] = s;
        bi[tid] = be - m * s;
    }
    for (int e = tid; e < M * K; e += NT)
        idxAll[e] = (unsigned short)((row0 + e / K < n) ? nbr[(size_t)row0 * K + e] : nin);
    __syncthreads();

    float4 acc[NTILE];
#pragma unroll
    for (int i = 0; i < NTILE; ++i) acc[i] = make_float4(0.f, 0.f, 0.f, 0.f);

    for (int k = 0; k < K; ++k) {
        if (k) __syncthreads();   // prev compute done before overwriting Xs/W
        // gather + bnrelu into Xs (row-major fp32)
        for (int e = tid; e < M * (CIN / 4); e += NT) {
            int r = e / (CIN / 4), c4 = e % (CIN / 4);
            int idx = idxAll[r * K + k];
            float4 v = make_float4(0.f, 0.f, 0.f, 0.f);
            int c = c4 * 4;
            if (idx < nin) {
                v = *(const float4*)(x + (size_t)idx * CIN + c);
                v.x = fmaxf(fmaf(v.x, sc[c + 0], bi[c + 0]), 0.f);
                v.y = fmaxf(fmaf(v.y, sc[c + 1], bi[c + 1]), 0.f);
                v.z = fmaxf(fmaf(v.z, sc[c + 2], bi[c + 2]), 0.f);
                v.w = fmaxf(fmaf(v.w, sc[c + 3], bi[c + 3]), 0.f);
            }
            *(float4*)(Xs + r * PX + c) = v;
        }
        // weights, pre-split hi/lo tf32
        const float* Wk = W + (size_t)k * CIN * COUT;
        for (int e = tid; e < CIN * COUT / 4; e += NT) {
            float4 w = *(const float4*)(Wk + e * 4);
            int ci = (e * 4) / COUT, c = (e * 4) % COUT;
            float4 h, l;
            h.x = __uint_as_float(tf32_of(w.x)); l.x = __uint_as_float(tf32_of(w.x - h.x));
            h.y = __uint_as_float(tf32_of(w.y)); l.y = __uint_as_float(tf32_of(w.y - h.y));
            h.z = __uint_as_float(tf32_of(w.z)); l.z = __uint_as_float(tf32_of(w.z - h.z));
            h.w = __uint_as_float(tf32_of(w.w)); l.w = __uint_as_float(tf32_of(w.w - h.w));
            *(float4*)(Whi + ci * PW + c) = h;
            *(float4*)(Wlo + ci * PW + c) = l;
        }
        __syncthreads();
        // compute: warp wid handles rows [wid*16, wid*16+16)
        int mrow = wid * 16;
#pragma unroll
        for (int ks = 0; ks < KS; ++ks) {
            int kb = ks * 8;
            float a0 = Xs[(mrow + grp) * PX + kb + tg];
            float a1 = Xs[(mrow + grp + 8) * PX + kb + tg];
            float a2 = Xs[(mrow + grp) * PX + kb + tg + 4];
            float a3 = Xs[(mrow + grp + 8) * PX + kb + tg + 4];
            uint32_t ah[4] = {tf32_of(a0), tf32_of(a1), tf32_of(a2), tf32_of(a3)};
            uint32_t al[4] = {tf32_of(a0 - __uint_as_float(ah[0])),
                              tf32_of(a1 - __uint_as_float(ah[1])),
                              tf32_of(a2 - __uint_as_float(ah[2])),
                              tf32_of(a3 - __uint_as_float(ah[3]))};
#pragma unroll
            for (int nt = 0; nt < NTILE; ++nt) {
                int nb = nt * 8 + grp;
                uint32_t bh[2] = {__float_as_uint(Whi[(kb + tg) * PW + nb]),
                                  __float_as_uint(Whi[(kb + tg + 4) * PW + nb])};
                uint32_t bl[2] = {__float_as_uint(Wlo[(kb + tg) * PW + nb]),
                                  __float_as_uint(Wlo[(kb + tg + 4) * PW + nb])};
                mma8(acc[nt], ah, bh);
                mma8(acc[nt], ah, bl);
                mma8(acc[nt], al, bh);
            }
        }
    }
    // epilogue: C frag -> global (+res)
    int r0 = row0 + wid * 16 + grp;
    int r1 = r0 + 8;
#pragma unroll
    for (int nt = 0; nt < NTILE; ++nt) {
        int c = nt * 8 + 2 * tg;
        if (r0 < n) {
            float2 v = make_float2(acc[nt].x, acc[nt].y);
            if (res) {
                float2 rv = *(const float2*)(res + (size_t)r0 * COUT + c);
                v.x += rv.x; v.y += rv.y;
            }
            *(float2*)(out + (size_t)r0 * COUT + c) = v;
        }
        if (r1 < n) {
            float2 v = make_float2(acc[nt].z, acc[nt].w);
            if (res) {
                float2 rv = *(const float2*)(res + (size_t)r1 * COUT + c);
                v.x += rv.x; v.y += rv.y;
            }
            *(float2*)(out + (size_t)r1 * COUT + c) = v;
        }
    }
}

// cat[i, 0:32] = identity[i,:]; cat[i, 32:64] = x1b[parent[i],:] @ up_W[kid[i]]
__global__ void up_concat(const float* __restrict__ idt, const float* __restrict__ x1,
                          const float* __restrict__ upW,
                          const int* __restrict__ parent, const int* __restrict__ kid,
                          float* __restrict__ cat, int n0) {
    int t = blockIdx.x * blockDim.x + threadIdx.x;
    if (t >= n0 * 64) return;
    int i = t / 64, c = t % 64;
    if (c < 32) {
        cat[t] = idt[(size_t)i * 32 + c];
    } else {
        const float* xr = x1 + (size_t)parent[i] * 64;
        const float* w = upW + (size_t)kid[i] * 64 * 32 + (c - 32);
        float a = 0.f;
#pragma unroll
        for (int ci = 0; ci < 64; ++ci) a += xr[ci] * w[ci * 32];
        cat[t] = a;
    }
}

__global__ void wsc_add(const float* __restrict__ h, const float* __restrict__ cat,
                        const float* __restrict__ Wsc, float* __restrict__ out, int n0) {
    int t = blockIdx.x * blockDim.x + threadIdx.x;
    if (t >= n0 * 32) return;
    int i = t / 32, c = t % 32;
    float a = h[t];
    const float* xr = cat + (size_t)i * 64;
#pragma unroll
    for (int ci = 0; ci < 64; ++ci) a += xr[ci] * Wsc[ci * 32 + c];
    out[t] = a;
}

// ---------------- host ----------------
static inline int ceil_div(int a, int b) { return (a + b - 1) / b; }
static inline int mma_smem(int cin, int cout, int K) {
    return 4 * 128 * (cin + 4) + 8 * cin * (cout + 4) + 2 * 128 * K + 8 * cin + 16;
}

extern "C" void kernel_launch(void* const* d_in, const int* in_sizes, int n_in,
                              void* d_out, int out_size) {
    const float* feats     = (const float*)d_in[0];
    const float* res0_W    = (const float*)d_in[1];
    const float* res0_bn   = (const float*)d_in[2];
    const float* down_bn   = (const float*)d_in[3];
    const float* down_W    = (const float*)d_in[4];
    const float* res1_W    = (const float*)d_in[5];
    const float* res1_bn   = (const float*)d_in[6];
    const float* up_bn     = (const float*)d_in[7];
    const float* up_W      = (const float*)d_in[8];
    const float* tail0_bn1 = (const float*)d_in[9];
    const float* tail0_W1  = (const float*)d_in[10];
    const float* tail0_bn2 = (const float*)d_in[11];
    const float* tail0_W2  = (const float*)d_in[12];
    const float* tail0_Wsc = (const float*)d_in[13];
    const float* tail1_W   = (const float*)d_in[14];
    const float* tail1_bn  = (const float*)d_in[15];
    const int* subm0_in    = (const int*)d_in[16];
    const int* subm0_out   = (const int*)d_in[17];
    const int* subm1_in    = (const int*)d_in[18];
    const int* subm1_out   = (const int*)d_in[19];
    const int* down_in     = (const int*)d_in[20];
    const int* down_out    = (const int*)d_in[21];
    const int* n1p         = (const int*)d_in[22];

    const int n0 = in_sizes[0] / 32;
    const int P0 = in_sizes[16] / 27;
    const int P1 = in_sizes[18] / 27;
    const int PD = in_sizes[20] / 8;

    float *f0a, *f0b, *f0c, *cat, *f1a, *f1b, *f1c;
    int *nbr0, *nbr1, *nbrD, *parent, *kid;
    cudaGetSymbolAddress((void**)&f0a, g_f0a);
    cudaGetSymbolAddress((void**)&f0b, g_f0b);
    cudaGetSymbolAddress((void**)&f0c, g_f0c);
    cudaGetSymbolAddress((void**)&cat, g_cat);
    cudaGetSymbolAddress((void**)&f1a, g_f1a);
    cudaGetSymbolAddress((void**)&f1b, g_f1b);
    cudaGetSymbolAddress((void**)&f1c, g_f1c);
    cudaGetSymbolAddress((void**)&nbr0, g_nbr0);
    cudaGetSymbolAddress((void**)&nbr1, g_nbr1);
    cudaGetSymbolAddress((void**)&nbrD, g_nbrD);
    cudaGetSymbolAddress((void**)&parent, g_parent);
    cudaGetSymbolAddress((void**)&kid, g_kid);

    const int S3232 = mma_smem(32, 32, 27);
    const int S3264 = mma_smem(32, 64, 8);
    const int S6464 = mma_smem(64, 64, 27);
    const int S6432 = mma_smem(64, 32, 27);
    cudaFuncSetAttribute(conv_mma<32, 32>, cudaFuncAttributeMaxDynamicSharedMemorySize, S3232);
    cudaFuncSetAttribute(conv_mma<32, 64>, cudaFuncAttributeMaxDynamicSharedMemorySize, S3264);
    cudaFuncSetAttribute(conv_mma<64, 64>, cudaFuncAttributeMaxDynamicSharedMemorySize, S6464);
    cudaFuncSetAttribute(conv_mma<64, 32>, cudaFuncAttributeMaxDynamicSharedMemorySize, S6432);

    const int TB = 256;
    const int G0 = ceil_div(n0, 128);
    const int G1 = ceil_div(N1MAX, 128);
    const int E164 = (N1MAX + 1) * 64;

    // ---- level-0 rulebook, then res0 convs (launch #6 = conv for ncu -s 5) ----
    fill_i32<<<ceil_div((N0 + 1) * 27, TB), TB>>>(nbr0, (N0 + 1) * 27, n0, nullptr);
    scatter_pairs<<<ceil_div(27 * P0, TB), TB>>>(subm0_in, subm0_out, 27 * P0, P0, 27, nbr0);

    const float* x = feats;
    for (int rep = 0; rep < 2; ++rep) {
        conv_mma<32, 32><<<G0, 256, S3232>>>(
            x, res0_bn + (rep * 2 + 0) * 128, res0_W + (size_t)(rep * 2 + 0) * 27 * 1024,
            nbr0, 27, nullptr, f0c, n0, nullptr, n0, nullptr);
        conv_mma<32, 32><<<G0, 256, S3232>>>(
            f0c, res0_bn + (rep * 2 + 1) * 128, res0_W + (size_t)(rep * 2 + 1) * 27 * 1024,
            nbr0, 27, x, f0a, n0, nullptr, n0, nullptr);
        x = f0a;
    }
    // f0a = identity

    fill_i32<<<ceil_div((N1MAX + 1) * 27, TB), TB>>>(nbr1, (N1MAX + 1) * 27, 0, n1p);
    scatter_pairs<<<ceil_div(27 * P1, TB), TB>>>(subm1_in, subm1_out, 27 * P1, P1, 27, nbr1);
    fill_i32<<<ceil_div((N1MAX + 1) * 8, TB), TB>>>(nbrD, (N1MAX + 1) * 8, n0, nullptr);
    scatter_pairs<<<ceil_div(8 * PD, TB), TB>>>(down_in, down_out, 8 * PD, PD, 8, nbrD);
    fill_i32<<<ceil_div(N0 + 1, TB), TB>>>(parent, N0 + 1, 0, n1p);
    fill_i32<<<ceil_div(N0 + 1, TB), TB>>>(kid, N0 + 1, 0, nullptr);
    scatter_parent<<<ceil_div(8 * PD, TB), TB>>>(down_in, down_out, 8 * PD, PD, n0, parent, kid);

    // ---- down conv (n_out = n1 dev, n_in = n0) ----
    conv_mma<32, 64><<<G1, 256, S3264>>>(f0a, down_bn, down_W, nbrD, 8,
                                         nullptr, f1a, 0, n1p, n0, nullptr);

    // ---- res1 blocks (level 1, C=64) ----
    for (int rep = 0; rep < 2; ++rep) {
        conv_mma<64, 64><<<G1, 256, S6464>>>(
            f1a, res1_bn + (rep * 2 + 0) * 256, res1_W + (size_t)(rep * 2 + 0) * 27 * 4096,
            nbr1, 27, nullptr, f1c, 0, n1p, 0, n1p);
        conv_mma<64, 64><<<G1, 256, S6464>>>(
            f1c, res1_bn + (rep * 2 + 1) * 256, res1_W + (size_t)(rep * 2 + 1) * 27 * 4096,
            nbr1, 27, f1a, f1a, 0, n1p, 0, n1p);
    }

    // ---- up conv + concat ----
    bnrelu_k<64><<<ceil_div(E164, TB), TB>>>(f1a, up_bn, f1b, 0, n1p, E164);
    up_concat<<<ceil_div(n0 * 64, TB), TB>>>(f0a, f1b, up_W, parent, kid, cat, n0);

    // ---- tail0 ----
    conv_mma<64, 32><<<G0, 256, S6432>>>(cat, tail0_bn1, tail0_W1, nbr0, 27,
                                         nullptr, f0b, n0, nullptr, n0, nullptr);
    conv_mma<32, 32><<<G0, 256, S3232>>>(f0b, tail0_bn2, tail0_W2, nbr0, 27,
                                         nullptr, f0c, n0, nullptr, n0, nullptr);
    wsc_add<<<ceil_div(n0 * 32, TB), TB>>>(f0c, cat, tail0_Wsc, f0b, n0);

    // ---- tail1 res block -> d_out ----
    conv_mma<32, 32><<<G0, 256, S3232>>>(f0b, tail1_bn + 0, tail1_W, nbr0, 27,
                                         nullptr, f0a, n0, nullptr, n0, nullptr);
    conv_mma<32, 32><<<G0, 256, S3232>>>(f0a, tail1_bn + 128, tail1_W + 27 * 1024, nbr0, 27,
                                         f0b, (float*)d_out, n0, nullptr, n0, nullptr);
}

// round 14
// speedup vs baseline: 2.0624x; 2.0624x over previous
#include <cuda_runtime.h>
#include <cuda_bf16.h>
#include <cstdint>

#define N0 48000
#define N1MAX 32000
#define EPSV 1e-4f

__device__ float g_f0a[(N0 + 1) * 32];
__device__ float g_f0b[(N0 + 1) * 32];
__device__ float g_f0c[(N0 + 1) * 32];
__device__ float g_cat[(N0 + 1) * 64];
__device__ float g_f1a[(N1MAX + 1) * 64];
__device__ float g_f1b[(N1MAX + 1) * 64];
__device__ float g_f1c[(N1MAX + 1) * 64];
__device__ int g_nbr0[(N0 + 1) * 27];
__device__ int g_nbr1[(N1MAX + 1) * 27];
__device__ int g_nbrD[(N1MAX + 1) * 8];
__device__ int g_parent[N0 + 1];
__device__ int g_kid[N0 + 1];
// pre-split transposed weights (bf16 hi/lo); 16B-aligned for uint4 loads
__device__ __align__(16) uint16_t g_wh[707584];
__device__ __align__(16) uint16_t g_wl[707584];

// weight segment offsets (elems)
#define WOFF_RES0   0        // 108 taps 32x32 (4 convs x 27)
#define WOFF_T0W2   110592   // 27 taps 32x32
#define WOFF_T1     138240   // 54 taps 32x32 (2 convs)
#define WOFF_T0W1   193536   // 27 taps cin64 cout32
#define WOFF_DOWN   248832   // 8 taps cin32 cout64
#define WOFF_RES1   265216   // 108 taps 64x64
#define WTOTAL      707584

// ---------------- helpers ----------------
__device__ __forceinline__ void bfsplit(float v, uint16_t& h, uint16_t& l) {
    __nv_bfloat16 hb = __float2bfloat16_rn(v);
    float r = v - __bfloat162float(hb);
    __nv_bfloat16 lb = __float2bfloat16_rn(r);
    h = *reinterpret_cast<uint16_t*>(&hb);
    l = *reinterpret_cast<uint16_t*>(&lb);
}
__device__ __forceinline__ uint32_t pk(uint16_t a, uint16_t b) {
    return (uint32_t)a | ((uint32_t)b << 16);
}
__device__ __forceinline__ void mma16(float4& d, const uint32_t* a, const uint32_t* b) {
    asm volatile(
        "mma.sync.aligned.m16n8k16.row.col.f32.bf16.bf16.f32 "
        "{%0,%1,%2,%3}, {%4,%5,%6,%7}, {%8,%9}, {%0,%1,%2,%3};"
        : "+f"(d.x), "+f"(d.y), "+f"(d.z), "+f"(d.w)
        : "r"(a[0]), "r"(a[1]), "r"(a[2]), "r"(a[3]), "r"(b[0]), "r"(b[1]));
}

// ---------------- setup kernels ----------------
__global__ void fill_i32(int* p, int count, int val, const int* vptr) {
    int t = blockIdx.x * blockDim.x + threadIdx.x;
    if (t >= count) return;
    p[t] = vptr ? *vptr : val;
}

__global__ void scatter_pairs(const int* __restrict__ pin, const int* __restrict__ pout,
                              int total, int P, int K, int* __restrict__ nbr) {
    int t = blockIdx.x * blockDim.x + threadIdx.x;
    if (t >= total) return;
    int k = t / P;
    nbr[pout[t] * K + k] = pin[t];
}

__global__ void scatter_parent(const int* __restrict__ din, const int* __restrict__ dout,
                               int total, int P, int n0,
                               int* __restrict__ parent, int* __restrict__ kid) {
    int t = blockIdx.x * blockDim.x + threadIdx.x;
    if (t >= total) return;
    int k = t / P;
    int i = din[t];
    if (i < n0) { parent[i] = dout[t]; kid[i] = k; }
}

// one launch: transpose+split ALL conv weights into g_wh/g_wl
__global__ void wsplit_all(const float* __restrict__ res0, const float* __restrict__ t0w2,
                           const float* __restrict__ t1w, const float* __restrict__ t0w1,
                           const float* __restrict__ dW, const float* __restrict__ r1w,
                           uint16_t* __restrict__ wh, uint16_t* __restrict__ wl) {
    int e = blockIdx.x * blockDim.x + threadIdx.x;
    if (e >= WTOTAL) return;
    const float* src;
    int base, cin, cout;
    if (e < WOFF_T0W2)      { src = res0; base = WOFF_RES0; cin = 32; cout = 32; }
    else if (e < WOFF_T1)   { src = t0w2; base = WOFF_T0W2; cin = 32; cout = 32; }
    else if (e < WOFF_T0W1) { src = t1w;  base = WOFF_T1;   cin = 32; cout = 32; }
    else if (e < WOFF_DOWN) { src = t0w1; base = WOFF_T0W1; cin = 64; cout = 32; }
    else if (e < WOFF_RES1) { src = dW;   base = WOFF_DOWN; cin = 32; cout = 64; }
    else                    { src = r1w;  base = WOFF_RES1; cin = 64; cout = 64; }
    int rel = e - base, tc = cin * cout;
    int tap = rel / tc, r = rel % tc, k = r / cout, n = r % cout;
    float w = src[rel];
    uint16_t h, l;
    bfsplit(w, h, l);
    int dst = base + tap * tc + n * cin + k;
    wh[dst] = h;
    wl[dst] = l;
}

template <int C>
__global__ void bnrelu_k(const float* __restrict__ x, const float* __restrict__ bn,
                         float* __restrict__ y, int n_host, const int* __restrict__ n_dev,
                         int total) {
    int t = blockIdx.x * blockDim.x + threadIdx.x;
    if (t >= total) return;
    int n = n_dev ? *n_dev : n_host;
    int r = t / C, c = t % C;
    float v = 0.f;
    if (r < n) {
        float g = bn[c], be = bn[C + c], m = bn[2 * C + c], va = bn[3 * C + c];
        v = fmaxf((x[t] - m) * (g * rsqrtf(va + EPSV)) + be, 0.f);
    }
    y[t] = v;
}

// ---------------- bf16x3 mma.sync gather implicit-GEMM sparse conv --------
// out[r,:] = sum_k bnrelu(x[nbr[r][k],:]) @ W[k]  (+ res[r,:])
// M=128 rows, 8 warps; warp owns 16 rows x COUT. A,W split hi/lo bf16;
// 3 MMAs per frag-pair (AhBh + AhBl + AlBh), m16n8k16.
template <int CIN, int COUT>
__global__ void __launch_bounds__(256)
conv_bf(const float* __restrict__ x, const float* __restrict__ bn,
        const uint16_t* __restrict__ whG, const uint16_t* __restrict__ wlG, int woff,
        const int* __restrict__ nbr, int K,
        const float* __restrict__ res, float* __restrict__ out,
        int nout_h, const int* __restrict__ nout_d,
        int nin_h, const int* __restrict__ nin_d) {
    constexpr int M = 128;
    constexpr int PXB = CIN / 2 + 4;   // b32 pitch, multiple of 4 -> 16B-aligned rows
    constexpr int NT = 256;
    constexpr int KC = CIN / 16;
    constexpr int NTILE = COUT / 8;
    extern __shared__ uint32_t smem[];
    uint32_t* Xh = smem;                       // M * PXB
    uint32_t* Xl = Xh + M * PXB;               // M * PXB
    uint32_t* Wh = Xl + M * PXB;               // COUT * PXB
    uint32_t* Wl = Wh + COUT * PXB;            // COUT * PXB
    unsigned short* idxAll = (unsigned short*)(Wl + COUT * PXB);   // M*K
    float* sc = (float*)(idxAll + M * K);
    float* bi = sc + CIN;

    int n = nout_d ? *nout_d : nout_h;
    int nin = nin_d ? *nin_d : nin_h;
    int row0 = blockIdx.x * M;
    if (row0 >= n) return;
    int tid = threadIdx.x, wid = tid >> 5, lane = tid & 31;
    int grp = lane >> 2, tg = lane & 3;

    if (tid < CIN) {
        float g = bn[tid], be = bn[CIN + tid], m = bn[2 * CIN + tid], va = bn[3 * CIN + tid];
        float s = g * rsqrtf(va + EPSV);
        sc[tid] = s;
        bi[tid] = be - m * s;
    }
    for (int e = tid; e < M * K; e += NT)
        idxAll[e] = (unsigned short)((row0 + e / K < n) ? nbr[(size_t)row0 * K + e] : nin);
    __syncthreads();

    float4 acc[NTILE];
#pragma unroll
    for (int i = 0; i < NTILE; ++i) acc[i] = make_float4(0.f, 0.f, 0.f, 0.f);

    for (int k = 0; k < K; ++k) {
        if (k) __syncthreads();
        // gather + bnrelu + bf16 hi/lo split into Xh/Xl
        for (int e = tid; e < M * (CIN / 4); e += NT) {
            int r = e / (CIN / 4), c4 = e % (CIN / 4);
            int idx = idxAll[r * K + k];
            float4 v = make_float4(0.f, 0.f, 0.f, 0.f);
            int c = c4 * 4;
            if (idx < nin) {
                v = *(const float4*)(x + (size_t)idx * CIN + c);
                v.x = fmaxf(fmaf(v.x, sc[c + 0], bi[c + 0]), 0.f);
                v.y = fmaxf(fmaf(v.y, sc[c + 1], bi[c + 1]), 0.f);
                v.z = fmaxf(fmaf(v.z, sc[c + 2], bi[c + 2]), 0.f);
                v.w = fmaxf(fmaf(v.w, sc[c + 3], bi[c + 3]), 0.f);
            }
            uint16_t h0, l0, h1, l1, h2, l2, h3, l3;
            bfsplit(v.x, h0, l0);
            bfsplit(v.y, h1, l1);
            bfsplit(v.z, h2, l2);
            bfsplit(v.w, h3, l3);
            Xh[r * PXB + c4 * 2 + 0] = pk(h0, h1);
            Xh[r * PXB + c4 * 2 + 1] = pk(h2, h3);
            Xl[r * PXB + c4 * 2 + 0] = pk(l0, l1);
            Xl[r * PXB + c4 * 2 + 1] = pk(l2, l3);
        }
        // W: straight copy from pre-split transposed planes [n][k]
        const uint16_t* wh = whG + woff + (size_t)k * CIN * COUT;
        const uint16_t* wl = wlG + woff + (size_t)k * CIN * COUT;
        for (int e = tid; e < COUT * (CIN / 8); e += NT) {
            int nr = e / (CIN / 8), seg = e % (CIN / 8);
            *(uint4*)(Wh + nr * PXB + seg * 4) = *(const uint4*)(wh + nr * CIN + seg * 8);
            *(uint4*)(Wl + nr * PXB + seg * 4) = *(const uint4*)(wl + nr * CIN + seg * 8);
        }
        __syncthreads();
        // compute
        int mrow = wid * 16;
#pragma unroll
        for (int kc = 0; kc < KC; ++kc) {
            int c0 = kc * 8 + tg;
            uint32_t ah[4], al[4];
            ah[0] = Xh[(mrow + grp) * PXB + c0];
            ah[1] = Xh[(mrow + grp + 8) * PXB + c0];
            ah[2] = Xh[(mrow + grp) * PXB + c0 + 4];
            ah[3] = Xh[(mrow + grp + 8) * PXB + c0 + 4];
            al[0] = Xl[(mrow + grp) * PXB + c0];
            al[1] = Xl[(mrow + grp + 8) * PXB + c0];
            al[2] = Xl[(mrow + grp) * PXB + c0 + 4];
            al[3] = Xl[(mrow + grp + 8) * PXB + c0 + 4];
#pragma unroll
            for (int nt = 0; nt < NTILE; ++nt) {
                int nb = nt * 8 + grp;
                uint32_t bh[2] = {Wh[nb * PXB + c0], Wh[nb * PXB + c0 + 4]};
                uint32_t bl[2] = {Wl[nb * PXB + c0], Wl[nb * PXB + c0 + 4]};
                mma16(acc[nt], ah, bh);
                mma16(acc[nt], ah, bl);
                mma16(acc[nt], al, bh);
            }
        }
    }
    // epilogue: C frag -> global (+res)
    int r0 = row0 + wid * 16 + grp;
    int r1 = r0 + 8;
#pragma unroll
    for (int nt = 0; nt < NTILE; ++nt) {
        int c = nt * 8 + 2 * tg;
        if (r0 < n) {
            float2 v = make_float2(acc[nt].x, acc[nt].y);
            if (res) {
                float2 rv = *(const float2*)(res + (size_t)r0 * COUT + c);
                v.x += rv.x; v.y += rv.y;
            }
            *(float2*)(out + (size_t)r0 * COUT + c) = v;
        }
        if (r1 < n) {
            float2 v = make_float2(acc[nt].z, acc[nt].w);
            if (res) {
                float2 rv = *(const float2*)(res + (size_t)r1 * COUT + c);
                v.x += rv.x; v.y += rv.y;
            }
            *(float2*)(out + (size_t)r1 * COUT + c) = v;
        }
    }
}

// cat[i, 0:32] = identity[i,:]; cat[i, 32:64] = x1b[parent[i],:] @ up_W[kid[i]]
__global__ void up_concat(const float* __restrict__ idt, const float* __restrict__ x1,
                          const float* __restrict__ upW,
                          const int* __restrict__ parent, const int* __restrict__ kid,
                          float* __restrict__ cat, int n0) {
    int t = blockIdx.x * blockDim.x + threadIdx.x;
    if (t >= n0 * 64) return;
    int i = t / 64, c = t % 64;
    if (c < 32) {
        cat[t] = idt[(size_t)i * 32 + c];
    } else {
        const float* xr = x1 + (size_t)parent[i] * 64;
        const float* w = upW + (size_t)kid[i] * 64 * 32 + (c - 32);
        float a = 0.f;
#pragma unroll
        for (int ci = 0; ci < 64; ++ci) a += xr[ci] * w[ci * 32];
        cat[t] = a;
    }
}

__global__ void wsc_add(const float* __restrict__ h, const float* __restrict__ cat,
                        const float* __restrict__ Wsc, float* __restrict__ out, int n0) {
    int t = blockIdx.x * blockDim.x + threadIdx.x;
    if (t >= n0 * 32) return;
    int i = t / 32, c = t % 32;
    float a = h[t];
    const float* xr = cat + (size_t)i * 64;
#pragma unroll
    for (int ci = 0; ci < 64; ++ci) a += xr[ci] * Wsc[ci * 32 + c];
    out[t] = a;
}

// ---------------- host ----------------
static inline int ceil_div(int a, int b) { return (a + b - 1) / b; }
static inline int bf_smem(int cin, int cout, int K) {
    int pxb = cin / 2 + 4;
    return 4 * (2 * 128 * pxb + 2 * cout * pxb) + 2 * 128 * K + 8 * cin + 16;
}

extern "C" void kernel_launch(void* const* d_in, const int* in_sizes, int n_in,
                              void* d_out, int out_size) {
    const float* feats     = (const float*)d_in[0];
    const float* res0_W    = (const float*)d_in[1];
    const float* res0_bn   = (const float*)d_in[2];
    const float* down_bn   = (const float*)d_in[3];
    const float* down_W    = (const float*)d_in[4];
    const float* res1_W    = (const float*)d_in[5];
    const float* res1_bn   = (const float*)d_in[6];
    const float* up_bn     = (const float*)d_in[7];
    const float* up_W      = (const float*)d_in[8];
    const float* tail0_bn1 = (const float*)d_in[9];
    const float* tail0_W1  = (const float*)d_in[10];
    const float* tail0_bn2 = (const float*)d_in[11];
    const float* tail0_W2  = (const float*)d_in[12];
    const float* tail0_Wsc = (const float*)d_in[13];
    const float* tail1_W   = (const float*)d_in[14];
    const float* tail1_bn  = (const float*)d_in[15];
    const int* subm0_in    = (const int*)d_in[16];
    const int* subm0_out   = (const int*)d_in[17];
    const int* subm1_in    = (const int*)d_in[18];
    const int* subm1_out   = (const int*)d_in[19];
    const int* down_in     = (const int*)d_in[20];
    const int* down_out    = (const int*)d_in[21];
    const int* n1p         = (const int*)d_in[22];

    const int n0 = in_sizes[0] / 32;
    const int P0 = in_sizes[16] / 27;
    const int P1 = in_sizes[18] / 27;
    const int PD = in_sizes[20] / 8;

    float *f0a, *f0b, *f0c, *cat, *f1a, *f1b, *f1c;
    int *nbr0, *nbr1, *nbrD, *parent, *kid;
    uint16_t *wh, *wl;
    cudaGetSymbolAddress((void**)&f0a, g_f0a);
    cudaGetSymbolAddress((void**)&f0b, g_f0b);
    cudaGetSymbolAddress((void**)&f0c, g_f0c);
    cudaGetSymbolAddress((void**)&cat, g_cat);
    cudaGetSymbolAddress((void**)&f1a, g_f1a);
    cudaGetSymbolAddress((void**)&f1b, g_f1b);
    cudaGetSymbolAddress((void**)&f1c, g_f1c);
    cudaGetSymbolAddress((void**)&nbr0, g_nbr0);
    cudaGetSymbolAddress((void**)&nbr1, g_nbr1);
    cudaGetSymbolAddress((void**)&nbrD, g_nbrD);
    cudaGetSymbolAddress((void**)&parent, g_parent);
    cudaGetSymbolAddress((void**)&kid, g_kid);
    cudaGetSymbolAddress((void**)&wh, g_wh);
    cudaGetSymbolAddress((void**)&wl, g_wl);

    const int S3232 = bf_smem(32, 32, 27);
    const int S3264 = bf_smem(32, 64, 8);
    const int S6464 = bf_smem(64, 64, 27);
    const int S6432 = bf_smem(64, 32, 27);
    cudaFuncSetAttribute(conv_bf<32, 32>, cudaFuncAttributeMaxDynamicSharedMemorySize, S3232);
    cudaFuncSetAttribute(conv_bf<32, 64>, cudaFuncAttributeMaxDynamicSharedMemorySize, S3264);
    cudaFuncSetAttribute(conv_bf<64, 64>, cudaFuncAttributeMaxDynamicSharedMemorySize, S6464);
    cudaFuncSetAttribute(conv_bf<64, 32>, cudaFuncAttributeMaxDynamicSharedMemorySize, S6432);

    const int TB = 256;
    const int G0 = ceil_div(n0, 128);
    const int G1 = ceil_div(N1MAX, 128);
    const int E164 = (N1MAX + 1) * 64;

    // ---- rulebook + weight prep, then res0 convs (launch #6 = conv) ----
    fill_i32<<<ceil_div((N0 + 1) * 27, TB), TB>>>(nbr0, (N0 + 1) * 27, n0, nullptr);          // 1
    scatter_pairs<<<ceil_div(27 * P0, TB), TB>>>(subm0_in, subm0_out, 27 * P0, P0, 27, nbr0);  // 2
    wsplit_all<<<ceil_div(WTOTAL, TB), TB>>>(res0_W, tail0_W2, tail1_W, tail0_W1,
                                             down_W, res1_W, wh, wl);                           // 3

    const float* x = feats;
    for (int rep = 0; rep < 2; ++rep) {                                                        // 4-7
        conv_bf<32, 32><<<G0, 256, S3232>>>(
            x, res0_bn + (rep * 2 + 0) * 128, wh, wl, WOFF_RES0 + (rep * 2 + 0) * 27648,
            nbr0, 27, nullptr, f0c, n0, nullptr, n0, nullptr);
        conv_bf<32, 32><<<G0, 256, S3232>>>(
            f0c, res0_bn + (rep * 2 + 1) * 128, wh, wl, WOFF_RES0 + (rep * 2 + 1) * 27648,
            nbr0, 27, x, f0a, n0, nullptr, n0, nullptr);
        x = f0a;
    }
    // f0a = identity

    fill_i32<<<ceil_div((N1MAX + 1) * 27, TB), TB>>>(nbr1, (N1MAX + 1) * 27, 0, n1p);
    scatter_pairs<<<ceil_div(27 * P1, TB), TB>>>(subm1_in, subm1_out, 27 * P1, P1, 27, nbr1);
    fill_i32<<<ceil_div((N1MAX + 1) * 8, TB), TB>>>(nbrD, (N1MAX + 1) * 8, n0, nullptr);
    scatter_pairs<<<ceil_div(8 * PD, TB), TB>>>(down_in, down_out, 8 * PD, PD, 8, nbrD);
    fill_i32<<<ceil_div(N0 + 1, TB), TB>>>(parent, N0 + 1, 0, n1p);
    fill_i32<<<ceil_div(N0 + 1, TB), TB>>>(kid, N0 + 1, 0, nullptr);
    scatter_parent<<<ceil_div(8 * PD, TB), TB>>>(down_in, down_out, 8 * PD, PD, n0, parent, kid);

    // ---- down conv (n_out = n1 dev, n_in = n0) ----
    conv_bf<32, 64><<<G1, 256, S3264>>>(f0a, down_bn, wh, wl, WOFF_DOWN, nbrD, 8,
                                        nullptr, f1a, 0, n1p, n0, nullptr);

    // ---- res1 blocks (level 1, C=64) ----
    for (int rep = 0; rep < 2; ++rep) {
        conv_bf<64, 64><<<G1, 256, S6464>>>(
            f1a, res1_bn + (rep * 2 + 0) * 256, wh, wl, WOFF_RES1 + (rep * 2 + 0) * 110592,
            nbr1, 27, nullptr, f1c, 0, n1p, 0, n1p);
        conv_bf<64, 64><<<G1, 256, S6464>>>(
            f1c, res1_bn + (rep * 2 + 1) * 256, wh, wl, WOFF_RES1 + (rep * 2 + 1) * 110592,
            nbr1, 27, f1a, f1a, 0, n1p, 0, n1p);
    }

    // ---- up conv + concat ----
    bnrelu_k<64><<<ceil_div(E164, TB), TB>>>(f1a, up_bn, f1b, 0, n1p, E164);
    up_concat<<<ceil_div(n0 * 64, TB), TB>>>(f0a, f1b, up_W, parent, kid, cat, n0);

    // ---- tail0 ----
    conv_bf<64, 32><<<G0, 256, S6432>>>(cat, tail0_bn1, wh, wl, WOFF_T0W1, nbr0, 27,
                                        nullptr, f0b, n0, nullptr, n0, nullptr);
    conv_bf<32, 32><<<G0, 256, S3232>>>(f0b, tail0_bn2, wh, wl, WOFF_T0W2, nbr0, 27,
                                        nullptr, f0c, n0, nullptr, n0, nullptr);
    wsc_add<<<ceil_div(n0 * 32, TB), TB>>>(f0c, cat, tail0_Wsc, f0b, n0);

    // ---- tail1 res block -> d_out ----
    conv_bf<32, 32><<<G0, 256, S3232>>>(f0b, tail1_bn + 0, wh, wl, WOFF_T1, nbr0, 27,
                                        nullptr, f0a, n0, nullptr, n0, nullptr);
    conv_bf<32, 32><<<G0, 256, S3232>>>(f0a, tail1_bn + 128, wh, wl, WOFF_T1 + 27648, nbr0, 27,
                                        f0b, (float*)d_out, n0, nullptr, n0, nullptr);
}

// round 15
// speedup vs baseline: 2.4179x; 1.1724x over previous
#include <cuda_runtime.h>
#include <cuda_bf16.h>
#include <cstdint>

#define N0 48000
#define N1MAX 32000
#define EPSV 1e-4f

__device__ float g_f0a[(N0 + 1) * 32];
__device__ float g_f0b[(N0 + 1) * 32];
__device__ float g_f0c[(N0 + 1) * 32];
__device__ float g_cat[(N0 + 1) * 64];
__device__ float g_f1a[(N1MAX + 1) * 64];
__device__ float g_f1b[(N1MAX + 1) * 64];
__device__ float g_f1c[(N1MAX + 1) * 64];
__device__ int g_nbr0[(N0 + 1) * 27];
__device__ int g_nbr1[(N1MAX + 1) * 27];
__device__ int g_nbrD[(N1MAX + 1) * 8];
__device__ int g_parent[N0 + 1];
__device__ int g_kid[N0 + 1];
// pre-split transposed weights (bf16 hi/lo); 16B-aligned for uint4 loads
__device__ __align__(16) uint16_t g_wh[707584];
__device__ __align__(16) uint16_t g_wl[707584];

#define WOFF_RES0   0
#define WOFF_T0W2   110592
#define WOFF_T1     138240
#define WOFF_T0W1   193536
#define WOFF_DOWN   248832
#define WOFF_RES1   265216
#define WTOTAL      707584

// ---------------- helpers ----------------
__device__ __forceinline__ void bfsplit(float v, uint16_t& h, uint16_t& l) {
    __nv_bfloat16 hb = __float2bfloat16_rn(v);
    float r = v - __bfloat162float(hb);
    __nv_bfloat16 lb = __float2bfloat16_rn(r);
    h = *reinterpret_cast<uint16_t*>(&hb);
    l = *reinterpret_cast<uint16_t*>(&lb);
}
__device__ __forceinline__ uint32_t pk(uint16_t a, uint16_t b) {
    return (uint32_t)a | ((uint32_t)b << 16);
}
__device__ __forceinline__ void mma16(float4& d, const uint32_t* a, const uint32_t* b) {
    asm volatile(
        "mma.sync.aligned.m16n8k16.row.col.f32.bf16.bf16.f32 "
        "{%0,%1,%2,%3}, {%4,%5,%6,%7}, {%8,%9}, {%0,%1,%2,%3};"
        : "+f"(d.x), "+f"(d.y), "+f"(d.z), "+f"(d.w)
        : "r"(a[0]), "r"(a[1]), "r"(a[2]), "r"(a[3]), "r"(b[0]), "r"(b[1]));
}

// ---------------- setup kernels ----------------
__global__ void fill_i32(int* p, int count, int val, const int* vptr) {
    int t = blockIdx.x * blockDim.x + threadIdx.x;
    if (t >= count) return;
    p[t] = vptr ? *vptr : val;
}

__global__ void scatter_pairs(const int* __restrict__ pin, const int* __restrict__ pout,
                              int total, int P, int K, int* __restrict__ nbr) {
    int t = blockIdx.x * blockDim.x + threadIdx.x;
    if (t >= total) return;
    int k = t / P;
    nbr[pout[t] * K + k] = pin[t];
}

__global__ void scatter_parent(const int* __restrict__ din, const int* __restrict__ dout,
                               int total, int P, int n0,
                               int* __restrict__ parent, int* __restrict__ kid) {
    int t = blockIdx.x * blockDim.x + threadIdx.x;
    if (t >= total) return;
    int k = t / P;
    int i = din[t];
    if (i < n0) { parent[i] = dout[t]; kid[i] = k; }
}

__global__ void wsplit_all(const float* __restrict__ res0, const float* __restrict__ t0w2,
                           const float* __restrict__ t1w, const float* __restrict__ t0w1,
                           const float* __restrict__ dW, const float* __restrict__ r1w,
                           uint16_t* __restrict__ wh, uint16_t* __restrict__ wl) {
    int e = blockIdx.x * blockDim.x + threadIdx.x;
    if (e >= WTOTAL) return;
    const float* src;
    int base, cin, cout;
    if (e < WOFF_T0W2)      { src = res0; base = WOFF_RES0; cin = 32; cout = 32; }
    else if (e < WOFF_T0W1) {
        if (e < WOFF_T1) { src = t0w2; base = WOFF_T0W2; }
        else             { src = t1w;  base = WOFF_T1; }
        cin = 32; cout = 32;
    }
    else if (e < WOFF_DOWN) { src = t0w1; base = WOFF_T0W1; cin = 64; cout = 32; }
    else if (e < WOFF_RES1) { src = dW;   base = WOFF_DOWN; cin = 32; cout = 64; }
    else                    { src = r1w;  base = WOFF_RES1; cin = 64; cout = 64; }
    int rel = e - base, tc = cin * cout;
    int tap = rel / tc, r = rel % tc, k = r / cout, n = r % cout;
    float w = src[rel];
    uint16_t h, l;
    bfsplit(w, h, l);
    int dst = base + tap * tc + n * cin + k;
    wh[dst] = h;
    wl[dst] = l;
}

template <int C>
__global__ void bnrelu_k(const float* __restrict__ x, const float* __restrict__ bn,
                         float* __restrict__ y, int n_host, const int* __restrict__ n_dev,
                         int total) {
    int t = blockIdx.x * blockDim.x + threadIdx.x;
    if (t >= total) return;
    int n = n_dev ? *n_dev : n_host;
    int r = t / C, c = t % C;
    float v = 0.f;
    if (r < n) {
        float g = bn[c], be = bn[C + c], m = bn[2 * C + c], va = bn[3 * C + c];
        v = fmaxf((x[t] - m) * (g * rsqrtf(va + EPSV)) + be, 0.f);
    }
    y[t] = v;
}

// ---------------- staging: gather+bnrelu+split A, copy W planes ----------
template <int CIN, int COUT, int BR, int NT>
__device__ __forceinline__ void stage_tile(
    const float* __restrict__ x, const uint16_t* __restrict__ whG,
    const uint16_t* __restrict__ wlG, const unsigned short* __restrict__ idxAll,
    int K, int k, int nin, const float* __restrict__ sc, const float* __restrict__ bi,
    uint32_t* __restrict__ Xh, uint32_t* __restrict__ Xl,
    uint32_t* __restrict__ Wh, uint32_t* __restrict__ Wl, int tid) {
    constexpr int PXB = CIN / 2 + 4;
#pragma unroll 1
    for (int e = tid; e < BR * (CIN / 4); e += NT) {
        int r = e / (CIN / 4), c4 = e % (CIN / 4);
        int idx = idxAll[r * K + k];
        float4 v = make_float4(0.f, 0.f, 0.f, 0.f);
        int c = c4 * 4;
        if (idx < nin) {
            v = *(const float4*)(x + (size_t)idx * CIN + c);
            v.x = fmaxf(fmaf(v.x, sc[c + 0], bi[c + 0]), 0.f);
            v.y = fmaxf(fmaf(v.y, sc[c + 1], bi[c + 1]), 0.f);
            v.z = fmaxf(fmaf(v.z, sc[c + 2], bi[c + 2]), 0.f);
            v.w = fmaxf(fmaf(v.w, sc[c + 3], bi[c + 3]), 0.f);
        }
        uint16_t h0, l0, h1, l1, h2, l2, h3, l3;
        bfsplit(v.x, h0, l0);
        bfsplit(v.y, h1, l1);
        bfsplit(v.z, h2, l2);
        bfsplit(v.w, h3, l3);
        Xh[r * PXB + c4 * 2 + 0] = pk(h0, h1);
        Xh[r * PXB + c4 * 2 + 1] = pk(h2, h3);
        Xl[r * PXB + c4 * 2 + 0] = pk(l0, l1);
        Xl[r * PXB + c4 * 2 + 1] = pk(l2, l3);
    }
    const uint16_t* wh = whG + (size_t)k * CIN * COUT;
    const uint16_t* wl = wlG + (size_t)k * CIN * COUT;
#pragma unroll 1
    for (int e = tid; e < COUT * (CIN / 8); e += NT) {
        int nr = e / (CIN / 8), seg = e % (CIN / 8);
        *(uint4*)(Wh + nr * PXB + seg * 4) = *(const uint4*)(wh + nr * CIN + seg * 8);
        *(uint4*)(Wl + nr * PXB + seg * 4) = *(const uint4*)(wl + nr * CIN + seg * 8);
    }
}

// ---------------- bf16x3 mma.sync gather implicit-GEMM sparse conv --------
// BR rows/tile; (BR/16) row-warps x CW col-warps. DB: double-buffered staging
// overlapped with compute, one barrier per tap.
template <int CIN, int COUT, int BR, int CW, bool DB>
__global__ void __launch_bounds__((BR / 16) * CW * 32)
conv_bf(const float* __restrict__ x, const float* __restrict__ bn,
        const uint16_t* __restrict__ whG, const uint16_t* __restrict__ wlG, int woff,
        const int* __restrict__ nbr, int K,
        const float* __restrict__ res, float* __restrict__ out,
        int nout_h, const int* __restrict__ nout_d,
        int nin_h, const int* __restrict__ nin_d) {
    constexpr int PXB = CIN / 2 + 4;
    constexpr int NT = (BR / 16) * CW * 32;
    constexpr int KC = CIN / 16;
    constexpr int CPW = COUT / CW;          // cols per warp
    constexpr int NTILE = CPW / 8;
    constexpr int SET = (2 * BR + 2 * COUT) * PXB;   // words per buffer set
    extern __shared__ uint32_t smem[];
    unsigned short* idxAll = (unsigned short*)(smem + (DB ? 2 : 1) * SET);  // BR*K
    float* sc = (float*)(idxAll + BR * K);
    float* bi = sc + CIN;

    int n = nout_d ? *nout_d : nout_h;
    int nin = nin_d ? *nin_d : nin_h;
    int row0 = blockIdx.x * BR;
    if (row0 >= n) return;
    int tid = threadIdx.x, wid = tid >> 5, lane = tid & 31;
    int grp = lane >> 2, tg = lane & 3;
    int rw = wid / CW, cw = wid % CW;
    int mrow = rw * 16, colbase = cw * CPW;

    if (tid < CIN) {
        float g = bn[tid], be = bn[CIN + tid], m = bn[2 * CIN + tid], va = bn[3 * CIN + tid];
        float s = g * rsqrtf(va + EPSV);
        sc[tid] = s;
        bi[tid] = be - m * s;
    }
    for (int e = tid; e < BR * K; e += NT)
        idxAll[e] = (unsigned short)((row0 + e / K < n) ? nbr[(size_t)row0 * K + e] : nin);
    __syncthreads();

    const uint16_t* whB = whG + woff;
    const uint16_t* wlB = wlG + woff;
    float4 acc[NTILE];
#pragma unroll
    for (int i = 0; i < NTILE; ++i) acc[i] = make_float4(0.f, 0.f, 0.f, 0.f);

    auto compute = [&](const uint32_t* Xh, const uint32_t* Xl,
                       const uint32_t* Wh, const uint32_t* Wl) {
#pragma unroll
        for (int kc = 0; kc < KC; ++kc) {
            int c0 = kc * 8 + tg;
            uint32_t ah[4], al[4];
            ah[0] = Xh[(mrow + grp) * PXB + c0];
            ah[1] = Xh[(mrow + grp + 8) * PXB + c0];
            ah[2] = Xh[(mrow + grp) * PXB + c0 + 4];
            ah[3] = Xh[(mrow + grp + 8) * PXB + c0 + 4];
            al[0] = Xl[(mrow + grp) * PXB + c0];
            al[1] = Xl[(mrow + grp + 8) * PXB + c0];
            al[2] = Xl[(mrow + grp) * PXB + c0 + 4];
            al[3] = Xl[(mrow + grp + 8) * PXB + c0 + 4];
#pragma unroll
            for (int nt = 0; nt < NTILE; ++nt) {
                int nb = colbase + nt * 8 + grp;
                uint32_t bh[2] = {Wh[nb * PXB + c0], Wh[nb * PXB + c0 + 4]};
                uint32_t bl[2] = {Wl[nb * PXB + c0], Wl[nb * PXB + c0 + 4]};
                mma16(acc[nt], ah, bh);
                mma16(acc[nt], ah, bl);
                mma16(acc[nt], al, bh);
            }
        }
    };
    auto bufp = [&](int b) { return smem + b * SET; };

    if (DB) {
        uint32_t* p0 = bufp(0);
        stage_tile<CIN, COUT, BR, NT>(x, whB, wlB, idxAll, K, 0, nin, sc, bi,
                                      p0, p0 + BR * PXB, p0 + 2 * BR * PXB,
                                      p0 + 2 * BR * PXB + COUT * PXB, tid);
        __syncthreads();
        for (int k = 0; k < K; ++k) {
            if (k + 1 < K) {
                uint32_t* pa = bufp((k + 1) & 1);
                stage_tile<CIN, COUT, BR, NT>(x, whB, wlB, idxAll, K, k + 1, nin, sc, bi,
                                              pa, pa + BR * PXB, pa + 2 * BR * PXB,
                                              pa + 2 * BR * PXB + COUT * PXB, tid);
            }
            uint32_t* pc = bufp(k & 1);
            compute(pc, pc + BR * PXB, pc + 2 * BR * PXB, pc + 2 * BR * PXB + COUT * PXB);
            __syncthreads();
        }
    } else {
        uint32_t* p0 = bufp(0);
        for (int k = 0; k < K; ++k) {
            if (k) __syncthreads();
            stage_tile<CIN, COUT, BR, NT>(x, whB, wlB, idxAll, K, k, nin, sc, bi,
                                          p0, p0 + BR * PXB, p0 + 2 * BR * PXB,
                                          p0 + 2 * BR * PXB + COUT * PXB, tid);
            __syncthreads();
            compute(p0, p0 + BR * PXB, p0 + 2 * BR * PXB, p0 + 2 * BR * PXB + COUT * PXB);
        }
    }

    // epilogue: C frag -> global (+res)
    int r0 = row0 + mrow + grp;
    int r1 = r0 + 8;
#pragma unroll
    for (int nt = 0; nt < NTILE; ++nt) {
        int c = colbase + nt * 8 + 2 * tg;
        if (r0 < n) {
            float2 v = make_float2(acc[nt].x, acc[nt].y);
            if (res) {
                float2 rv = *(const float2*)(res + (size_t)r0 * COUT + c);
                v.x += rv.x; v.y += rv.y;
            }
            *(float2*)(out + (size_t)r0 * COUT + c) = v;
        }
        if (r1 < n) {
            float2 v = make_float2(acc[nt].z, acc[nt].w);
            if (res) {
                float2 rv = *(const float2*)(res + (size_t)r1 * COUT + c);
                v.x += rv.x; v.y += rv.y;
            }
            *(float2*)(out + (size_t)r1 * COUT + c) = v;
        }
    }
}

// cat[i, 0:32] = identity[i,:]; cat[i, 32:64] = x1b[parent[i],:] @ up_W[kid[i]]
__global__ void up_concat(const float* __restrict__ idt, const float* __restrict__ x1,
                          const float* __restrict__ upW,
                          const int* __restrict__ parent, const int* __restrict__ kid,
                          float* __restrict__ cat, int n0) {
    int t = blockIdx.x * blockDim.x + threadIdx.x;
    if (t >= n0 * 64) return;
    int i = t / 64, c = t % 64;
    if (c < 32) {
        cat[t] = idt[(size_t)i * 32 + c];
    } else {
        const float* xr = x1 + (size_t)parent[i] * 64;
        const float* w = upW + (size_t)kid[i] * 64 * 32 + (c - 32);
        float a = 0.f;
#pragma unroll
        for (int ci = 0; ci < 64; ++ci) a += xr[ci] * w[ci * 32];
        cat[t] = a;
    }
}

__global__ void wsc_add(const float* __restrict__ h, const float* __restrict__ cat,
                        const float* __restrict__ Wsc, float* __restrict__ out, int n0) {
    int t = blockIdx.x * blockDim.x + threadIdx.x;
    if (t >= n0 * 32) return;
    int i = t / 32, c = t % 32;
    float a = h[t];
    const float* xr = cat + (size_t)i * 64;
#pragma unroll
    for (int ci = 0; ci < 64; ++ci) a += xr[ci] * Wsc[ci * 32 + c];
    out[t] = a;
}

// ---------------- host ----------------
static inline int ceil_div(int a, int b) { return (a + b - 1) / b; }
static inline int bf_smem(int cin, int cout, int K, int BR, bool db) {
    int pxb = cin / 2 + 4;
    int set = 4 * (2 * BR + 2 * cout) * pxb;
    return set * (db ? 2 : 1) + 2 * BR * K + 8 * cin + 16;
}

extern "C" void kernel_launch(void* const* d_in, const int* in_sizes, int n_in,
                              void* d_out, int out_size) {
    const float* feats     = (const float*)d_in[0];
    const float* res0_W    = (const float*)d_in[1];
    const float* res0_bn   = (const float*)d_in[2];
    const float* down_bn   = (const float*)d_in[3];
    const float* down_W    = (const float*)d_in[4];
    const float* res1_W    = (const float*)d_in[5];
    const float* res1_bn   = (const float*)d_in[6];
    const float* up_bn     = (const float*)d_in[7];
    const float* up_W      = (const float*)d_in[8];
    const float* tail0_bn1 = (const float*)d_in[9];
    const float* tail0_W1  = (const float*)d_in[10];
    const float* tail0_bn2 = (const float*)d_in[11];
    const float* tail0_W2  = (const float*)d_in[12];
    const float* tail0_Wsc = (const float*)d_in[13];
    const float* tail1_W   = (const float*)d_in[14];
    const float* tail1_bn  = (const float*)d_in[15];
    const int* subm0_in    = (const int*)d_in[16];
    const int* subm0_out   = (const int*)d_in[17];
    const int* subm1_in    = (const int*)d_in[18];
    const int* subm1_out   = (const int*)d_in[19];
    const int* down_in     = (const int*)d_in[20];
    const int* down_out    = (const int*)d_in[21];
    const int* n1p         = (const int*)d_in[22];

    const int n0 = in_sizes[0] / 32;
    const int P0 = in_sizes[16] / 27;
    const int P1 = in_sizes[18] / 27;
    const int PD = in_sizes[20] / 8;

    float *f0a, *f0b, *f0c, *cat, *f1a, *f1b, *f1c;
    int *nbr0, *nbr1, *nbrD, *parent, *kid;
    uint16_t *wh, *wl;
    cudaGetSymbolAddress((void**)&f0a, g_f0a);
    cudaGetSymbolAddress((void**)&f0b, g_f0b);
    cudaGetSymbolAddress((void**)&f0c, g_f0c);
    cudaGetSymbolAddress((void**)&cat, g_cat);
    cudaGetSymbolAddress((void**)&f1a, g_f1a);
    cudaGetSymbolAddress((void**)&f1b, g_f1b);
    cudaGetSymbolAddress((void**)&f1c, g_f1c);
    cudaGetSymbolAddress((void**)&nbr0, g_nbr0);
    cudaGetSymbolAddress((void**)&nbr1, g_nbr1);
    cudaGetSymbolAddress((void**)&nbrD, g_nbrD);
    cudaGetSymbolAddress((void**)&parent, g_parent);
    cudaGetSymbolAddress((void**)&kid, g_kid);
    cudaGetSymbolAddress((void**)&wh, g_wh);
    cudaGetSymbolAddress((void**)&wl, g_wl);

    const int S3232 = bf_smem(32, 32, 27, 128, true);
    const int S3264 = bf_smem(32, 64, 8, 128, true);
    const int S6464 = bf_smem(64, 64, 27, 64, false);
    const int S6432 = bf_smem(64, 32, 27, 128, false);
    cudaFuncSetAttribute((const void*)conv_bf<32, 32, 128, 1, true>,
                         cudaFuncAttributeMaxDynamicSharedMemorySize, S3232);
    cudaFuncSetAttribute((const void*)conv_bf<32, 64, 128, 1, true>,
                         cudaFuncAttributeMaxDynamicSharedMemorySize, S3264);
    cudaFuncSetAttribute((const void*)conv_bf<64, 64, 64, 2, false>,
                         cudaFuncAttributeMaxDynamicSharedMemorySize, S6464);
    cudaFuncSetAttribute((const void*)conv_bf<64, 32, 128, 1, false>,
                         cudaFuncAttributeMaxDynamicSharedMemorySize, S6432);

    const int TB = 256;
    const int G0 = ceil_div(n0, 128);
    const int G1_128 = ceil_div(N1MAX, 128);
    const int G1_64  = ceil_div(N1MAX, 64);
    const int E164 = (N1MAX + 1) * 64;

    // ---- rulebook + weight prep, then res0 convs (launch #6 = conv) ----
    fill_i32<<<ceil_div((N0 + 1) * 27, TB), TB>>>(nbr0, (N0 + 1) * 27, n0, nullptr);
    scatter_pairs<<<ceil_div(27 * P0, TB), TB>>>(subm0_in, subm0_out, 27 * P0, P0, 27, nbr0);
    wsplit_all<<<ceil_div(WTOTAL, TB), TB>>>(res0_W, tail0_W2, tail1_W, tail0_W1,
                                             down_W, res1_W, wh, wl);

    const float* x = feats;
    for (int rep = 0; rep < 2; ++rep) {
        conv_bf<32, 32, 128, 1, true><<<G0, 256, S3232>>>(
            x, res0_bn + (rep * 2 + 0) * 128, wh, wl, WOFF_RES0 + (rep * 2 + 0) * 27648,
            nbr0, 27, nullptr, f0c, n0, nullptr, n0, nullptr);
        conv_bf<32, 32, 128, 1, true><<<G0, 256, S3232>>>(
            f0c, res0_bn + (rep * 2 + 1) * 128, wh, wl, WOFF_RES0 + (rep * 2 + 1) * 27648,
            nbr0, 27, x, f0a, n0, nullptr, n0, nullptr);
        x = f0a;
    }
    // f0a = identity

    fill_i32<<<ceil_div((N1MAX + 1) * 27, TB), TB>>>(nbr1, (N1MAX + 1) * 27, 0, n1p);
    scatter_pairs<<<ceil_div(27 * P1, TB), TB>>>(subm1_in, subm1_out, 27 * P1, P1, 27, nbr1);
    fill_i32<<<ceil_div((N1MAX + 1) * 8, TB), TB>>>(nbrD, (N1MAX + 1) * 8, n0, nullptr);
    scatter_pairs<<<ceil_div(8 * PD, TB), TB>>>(down_in, down_out, 8 * PD, PD, 8, nbrD);
    fill_i32<<<ceil_div(N0 + 1, TB), TB>>>(parent, N0 + 1, 0, n1p);
    fill_i32<<<ceil_div(N0 + 1, TB), TB>>>(kid, N0 + 1, 0, nullptr);
    scatter_parent<<<ceil_div(8 * PD, TB), TB>>>(down_in, down_out, 8 * PD, PD, n0, parent, kid);

    // ---- down conv (n_out = n1 dev, n_in = n0) ----
    conv_bf<32, 64, 128, 1, true><<<G1_128, 256, S3264>>>(
        f0a, down_bn, wh, wl, WOFF_DOWN, nbrD, 8, nullptr, f1a, 0, n1p, n0, nullptr);

    // ---- res1 blocks (level 1, C=64): BR=64, 4x2 warps, grid 500 ----
    for (int rep = 0; rep < 2; ++rep) {
        conv_bf<64, 64, 64, 2, false><<<G1_64, 256, S6464>>>(
            f1a, res1_bn + (rep * 2 + 0) * 256, wh, wl, WOFF_RES1 + (rep * 2 + 0) * 110592,
            nbr1, 27, nullptr, f1c, 0, n1p, 0, n1p);
        conv_bf<64, 64, 64, 2, false><<<G1_64, 256, S6464>>>(
            f1c, res1_bn + (rep * 2 + 1) * 256, wh, wl, WOFF_RES1 + (rep * 2 + 1) * 110592,
            nbr1, 27, f1a, f1a, 0, n1p, 0, n1p);
    }

    // ---- up conv + concat ----
    bnrelu_k<64><<<ceil_div(E164, TB), TB>>>(f1a, up_bn, f1b, 0, n1p, E164);
    up_concat<<<ceil_div(n0 * 64, TB), TB>>>(f0a, f1b, up_W, parent, kid, cat, n0);

    // ---- tail0 ----
    conv_bf<64, 32, 128, 1, false><<<G0, 256, S6432>>>(
        cat, tail0_bn1, wh, wl, WOFF_T0W1, nbr0, 27, nullptr, f0b, n0, nullptr, n0, nullptr);
    conv_bf<32, 32, 128, 1, true><<<G0, 256, S3232>>>(
        f0b, tail0_bn2, wh, wl, WOFF_T0W2, nbr0, 27, nullptr, f0c, n0, nullptr, n0, nullptr);
    wsc_add<<<ceil_div(n0 * 32, TB), TB>>>(f0c, cat, tail0_Wsc, f0b, n0);

    // ---- tail1 res block -> d_out ----
    conv_bf<32, 32, 128, 1, true><<<G0, 256, S3232>>>(
        f0b, tail1_bn + 0, wh, wl, WOFF_T1, nbr0, 27, nullptr, f0a, n0, nullptr, n0, nullptr);
    conv_bf<32, 32, 128, 1, true><<<G0, 256, S3232>>>(
        f0a, tail1_bn + 128, wh, wl, WOFF_T1 + 27648, nbr0, 27,
        f0b, (float*)d_out, n0, nullptr, n0, nullptr);
}

// round 16
// speedup vs baseline: 2.7249x; 1.1270x over previous
#include <cuda_runtime.h>
#include <cuda_bf16.h>
#include <cstdint>

#define N0 48000
#define N1MAX 32000
#define EPSV 1e-4f

__device__ float g_f0a[(N0 + 1) * 32];
__device__ float g_f0b[(N0 + 1) * 32];
__device__ float g_f0c[(N0 + 1) * 32];
__device__ float g_cat[(N0 + 1) * 64];
__device__ float g_f1a[(N1MAX + 1) * 64];
__device__ float g_f1b[(N1MAX + 1) * 64];
__device__ float g_f1c[(N1MAX + 1) * 64];
__device__ int g_nbr0[(N0 + 1) * 27];
__device__ int g_nbr1[(N1MAX + 1) * 27];
__device__ int g_nbrD[(N1MAX + 1) * 8];
__device__ int g_parent[N0 + 1];
__device__ int g_kid[N0 + 1];
// pre-split transposed weights (bf16 hi/lo)
__device__ __align__(16) uint16_t g_wh[707584];
__device__ __align__(16) uint16_t g_wl[707584];
// pre-split bnrelu'd activations (packed bf16 pairs), reused serially per conv
__device__ __align__(16) uint32_t g_ph32[(N0 + 1) * 16];
__device__ __align__(16) uint32_t g_pl32[(N0 + 1) * 16];
__device__ __align__(16) uint32_t g_ph64[(N0 + 1) * 32];
__device__ __align__(16) uint32_t g_pl64[(N0 + 1) * 32];

#define WOFF_RES0   0
#define WOFF_T0W2   110592
#define WOFF_T1     138240
#define WOFF_T0W1   193536
#define WOFF_DOWN   248832
#define WOFF_RES1   265216
#define WTOTAL      707584

// ---------------- helpers ----------------
__device__ __forceinline__ void bfsplit(float v, uint16_t& h, uint16_t& l) {
    __nv_bfloat16 hb = __float2bfloat16_rn(v);
    float r = v - __bfloat162float(hb);
    __nv_bfloat16 lb = __float2bfloat16_rn(r);
    h = *reinterpret_cast<uint16_t*>(&hb);
    l = *reinterpret_cast<uint16_t*>(&lb);
}
__device__ __forceinline__ uint32_t pk(uint16_t a, uint16_t b) {
    return (uint32_t)a | ((uint32_t)b << 16);
}
__device__ __forceinline__ void mma16(float4& d, const uint32_t* a, const uint32_t* b) {
    asm volatile(
        "mma.sync.aligned.m16n8k16.row.col.f32.bf16.bf16.f32 "
        "{%0,%1,%2,%3}, {%4,%5,%6,%7}, {%8,%9}, {%0,%1,%2,%3};"
        : "+f"(d.x), "+f"(d.y), "+f"(d.z), "+f"(d.w)
        : "r"(a[0]), "r"(a[1]), "r"(a[2]), "r"(a[3]), "r"(b[0]), "r"(b[1]));
}

// ---------------- setup kernels ----------------
__global__ void fill_i32(int* p, int count, int val, const int* vptr) {
    int t = blockIdx.x * blockDim.x + threadIdx.x;
    if (t >= count) return;
    p[t] = vptr ? *vptr : val;
}

__global__ void scatter_pairs(const int* __restrict__ pin, const int* __restrict__ pout,
                              int total, int P, int K, int* __restrict__ nbr) {
    int t = blockIdx.x * blockDim.x + threadIdx.x;
    if (t >= total) return;
    int k = t / P;
    nbr[pout[t] * K + k] = pin[t];
}

__global__ void scatter_parent(const int* __restrict__ din, const int* __restrict__ dout,
                               int total, int P, int n0,
                               int* __restrict__ parent, int* __restrict__ kid) {
    int t = blockIdx.x * blockDim.x + threadIdx.x;
    if (t >= total) return;
    int k = t / P;
    int i = din[t];
    if (i < n0) { parent[i] = dout[t]; kid[i] = k; }
}

__global__ void wsplit_all(const float* __restrict__ res0, const float* __restrict__ t0w2,
                           const float* __restrict__ t1w, const float* __restrict__ t0w1,
                           const float* __restrict__ dW, const float* __restrict__ r1w,
                           uint16_t* __restrict__ wh, uint16_t* __restrict__ wl) {
    int e = blockIdx.x * blockDim.x + threadIdx.x;
    if (e >= WTOTAL) return;
    const float* src;
    int base, cin, cout;
    if (e < WOFF_T0W2)      { src = res0; base = WOFF_RES0; cin = 32; cout = 32; }
    else if (e < WOFF_T0W1) {
        if (e < WOFF_T1) { src = t0w2; base = WOFF_T0W2; }
        else             { src = t1w;  base = WOFF_T1; }
        cin = 32; cout = 32;
    }
    else if (e < WOFF_DOWN) { src = t0w1; base = WOFF_T0W1; cin = 64; cout = 32; }
    else if (e < WOFF_RES1) { src = dW;   base = WOFF_DOWN; cin = 32; cout = 64; }
    else                    { src = r1w;  base = WOFF_RES1; cin = 64; cout = 64; }
    int rel = e - base, tc = cin * cout;
    int tap = rel / tc, r = rel % tc, k = r / cout, n = r % cout;
    float w = src[rel];
    uint16_t h, l;
    bfsplit(w, h, l);
    int dst = base + tap * tc + n * cin + k;
    wh[dst] = h;
    wl[dst] = l;
}

// bnrelu + bf16 hi/lo split, packed pairs: one pass per conv input
template <int C>
__global__ void prep_bf(const float* __restrict__ x, const float* __restrict__ bn,
                        uint32_t* __restrict__ ph, uint32_t* __restrict__ pl,
                        int n_host, const int* __restrict__ n_dev, int total_pairs) {
    int t = blockIdx.x * blockDim.x + threadIdx.x;
    if (t >= total_pairs) return;
    int n = n_dev ? *n_dev : n_host;
    int r = t / (C / 2), j = t % (C / 2);
    uint32_t hw = 0, lw = 0;
    if (r < n) {
        int c0 = 2 * j, c1 = 2 * j + 1;
        float g0 = bn[c0], g1 = bn[c1];
        float s0 = g0 * rsqrtf(bn[3 * C + c0] + EPSV);
        float s1 = g1 * rsqrtf(bn[3 * C + c1] + EPSV);
        float b0 = bn[C + c0] - bn[2 * C + c0] * s0;
        float b1 = bn[C + c1] - bn[2 * C + c1] * s1;
        float2 v = *(const float2*)(x + (size_t)r * C + c0);
        v.x = fmaxf(fmaf(v.x, s0, b0), 0.f);
        v.y = fmaxf(fmaf(v.y, s1, b1), 0.f);
        uint16_t h0, l0, h1, l1;
        bfsplit(v.x, h0, l0);
        bfsplit(v.y, h1, l1);
        hw = pk(h0, h1);
        lw = pk(l0, l1);
    }
    ph[t] = hw;
    pl[t] = lw;
}

// ---------------- staging: pure copy of pre-split planes ----------
template <int CIN, int COUT, int BR, int NT>
__device__ __forceinline__ void stage_tile(
    const uint32_t* __restrict__ xh, const uint32_t* __restrict__ xl,
    const uint16_t* __restrict__ whG, const uint16_t* __restrict__ wlG,
    const unsigned short* __restrict__ idxAll, int K, int k, int nin,
    uint32_t* __restrict__ Xh, uint32_t* __restrict__ Xl,
    uint32_t* __restrict__ Wh, uint32_t* __restrict__ Wl, int tid) {
    constexpr int PXB = CIN / 2 + 4;
    const uint4 z4 = make_uint4(0u, 0u, 0u, 0u);
#pragma unroll 1
    for (int e = tid; e < BR * (CIN / 8); e += NT) {
        int r = e / (CIN / 8), seg = e % (CIN / 8);
        int idx = idxAll[r * K + k];
        uint4 h = z4, l = z4;
        if (idx < nin) {
            h = *(const uint4*)(xh + (size_t)idx * (CIN / 2) + seg * 4);
            l = *(const uint4*)(xl + (size_t)idx * (CIN / 2) + seg * 4);
        }
        *(uint4*)(Xh + r * PXB + seg * 4) = h;
        *(uint4*)(Xl + r * PXB + seg * 4) = l;
    }
    const uint16_t* wh = whG + (size_t)k * CIN * COUT;
    const uint16_t* wl = wlG + (size_t)k * CIN * COUT;
#pragma unroll 1
    for (int e = tid; e < COUT * (CIN / 8); e += NT) {
        int nr = e / (CIN / 8), seg = e % (CIN / 8);
        *(uint4*)(Wh + nr * PXB + seg * 4) = *(const uint4*)(wh + nr * CIN + seg * 8);
        *(uint4*)(Wl + nr * PXB + seg * 4) = *(const uint4*)(wl + nr * CIN + seg * 8);
    }
}

// ---------------- bf16x3 mma.sync gather implicit-GEMM sparse conv --------
template <int CIN, int COUT, int BR, int CW, bool DB>
__global__ void __launch_bounds__((BR / 16) * CW * 32)
conv_bf(const uint32_t* __restrict__ xh, const uint32_t* __restrict__ xl,
        const uint16_t* __restrict__ whG, const uint16_t* __restrict__ wlG, int woff,
        const int* __restrict__ nbr, int K,
        const float* __restrict__ res, float* __restrict__ out,
        int nout_h, const int* __restrict__ nout_d,
        int nin_h, const int* __restrict__ nin_d) {
    constexpr int PXB = CIN / 2 + 4;
    constexpr int NT = (BR / 16) * CW * 32;
    constexpr int KC = CIN / 16;
    constexpr int CPW = COUT / CW;
    constexpr int NTILE = CPW / 8;
    constexpr int SET = (2 * BR + 2 * COUT) * PXB;
    extern __shared__ uint32_t smem[];
    unsigned short* idxAll = (unsigned short*)(smem + (DB ? 2 : 1) * SET);

    int n = nout_d ? *nout_d : nout_h;
    int nin = nin_d ? *nin_d : nin_h;
    int row0 = blockIdx.x * BR;
    if (row0 >= n) return;
    int tid = threadIdx.x, wid = tid >> 5, lane = tid & 31;
    int grp = lane >> 2, tg = lane & 3;
    int rw = wid / CW, cw = wid % CW;
    int mrow = rw * 16, colbase = cw * CPW;

    for (int e = tid; e < BR * K; e += NT)
        idxAll[e] = (unsigned short)((row0 + e / K < n) ? nbr[(size_t)row0 * K + e] : nin);
    __syncthreads();

    const uint16_t* whB = whG + woff;
    const uint16_t* wlB = wlG + woff;
    float4 acc[NTILE];
#pragma unroll
    for (int i = 0; i < NTILE; ++i) acc[i] = make_float4(0.f, 0.f, 0.f, 0.f);

    auto compute = [&](const uint32_t* Xh, const uint32_t* Xl,
                       const uint32_t* Wh, const uint32_t* Wl) {
#pragma unroll
        for (int kc = 0; kc < KC; ++kc) {
            int c0 = kc * 8 + tg;
            uint32_t ah[4], al[4];
            ah[0] = Xh[(mrow + grp) * PXB + c0];
            ah[1] = Xh[(mrow + grp + 8) * PXB + c0];
            ah[2] = Xh[(mrow + grp) * PXB + c0 + 4];
            ah[3] = Xh[(mrow + grp + 8) * PXB + c0 + 4];
            al[0] = Xl[(mrow + grp) * PXB + c0];
            al[1] = Xl[(mrow + grp + 8) * PXB + c0];
            al[2] = Xl[(mrow + grp) * PXB + c0 + 4];
            al[3] = Xl[(mrow + grp + 8) * PXB + c0 + 4];
#pragma unroll
            for (int nt = 0; nt < NTILE; ++nt) {
                int nb = colbase + nt * 8 + grp;
                uint32_t bh[2] = {Wh[nb * PXB + c0], Wh[nb * PXB + c0 + 4]};
                uint32_t bl[2] = {Wl[nb * PXB + c0], Wl[nb * PXB + c0 + 4]};
                mma16(acc[nt], ah, bh);
                mma16(acc[nt], ah, bl);
                mma16(acc[nt], al, bh);
            }
        }
    };
    auto bufp = [&](int b) { return smem + b * SET; };

    if (DB) {
        uint32_t* p0 = bufp(0);
        stage_tile<CIN, COUT, BR, NT>(xh, xl, whB, wlB, idxAll, K, 0, nin,
                                      p0, p0 + BR * PXB, p0 + 2 * BR * PXB,
                                      p0 + 2 * BR * PXB + COUT * PXB, tid);
        __syncthreads();
        for (int k = 0; k < K; ++k) {
            if (k + 1 < K) {
                uint32_t* pa = bufp((k + 1) & 1);
                stage_tile<CIN, COUT, BR, NT>(xh, xl, whB, wlB, idxAll, K, k + 1, nin,
                                              pa, pa + BR * PXB, pa + 2 * BR * PXB,
                                              pa + 2 * BR * PXB + COUT * PXB, tid);
            }
            uint32_t* pc = bufp(k & 1);
            compute(pc, pc + BR * PXB, pc + 2 * BR * PXB, pc + 2 * BR * PXB + COUT * PXB);
            __syncthreads();
        }
    } else {
        uint32_t* p0 = bufp(0);
        for (int k = 0; k < K; ++k) {
            if (k) __syncthreads();
            stage_tile<CIN, COUT, BR, NT>(xh, xl, whB, wlB, idxAll, K, k, nin,
                                          p0, p0 + BR * PXB, p0 + 2 * BR * PXB,
                                          p0 + 2 * BR * PXB + COUT * PXB, tid);
            __syncthreads();
            compute(p0, p0 + BR * PXB, p0 + 2 * BR * PXB, p0 + 2 * BR * PXB + COUT * PXB);
        }
    }

    int r0 = row0 + mrow + grp;
    int r1 = r0 + 8;
#pragma unroll
    for (int nt = 0; nt < NTILE; ++nt) {
        int c = colbase + nt * 8 + 2 * tg;
        if (r0 < n) {
            float2 v = make_float2(acc[nt].x, acc[nt].y);
            if (res) {
                float2 rv = *(const float2*)(res + (size_t)r0 * COUT + c);
                v.x += rv.x; v.y += rv.y;
            }
            *(float2*)(out + (size_t)r0 * COUT + c) = v;
        }
        if (r1 < n) {
            float2 v = make_float2(acc[nt].z, acc[nt].w);
            if (res) {
                float2 rv = *(const float2*)(res + (size_t)r1 * COUT + c);
                v.x += rv.x; v.y += rv.y;
            }
            *(float2*)(out + (size_t)r1 * COUT + c) = v;
        }
    }
}

template <int C>
__global__ void bnrelu_k(const float* __restrict__ x, const float* __restrict__ bn,
                         float* __restrict__ y, int n_host, const int* __restrict__ n_dev,
                         int total) {
    int t = blockIdx.x * blockDim.x + threadIdx.x;
    if (t >= total) return;
    int n = n_dev ? *n_dev : n_host;
    int r = t / C, c = t % C;
    float v = 0.f;
    if (r < n) {
        float g = bn[c], be = bn[C + c], m = bn[2 * C + c], va = bn[3 * C + c];
        v = fmaxf((x[t] - m) * (g * rsqrtf(va + EPSV)) + be, 0.f);
    }
    y[t] = v;
}

__global__ void up_concat(const float* __restrict__ idt, const float* __restrict__ x1,
                          const float* __restrict__ upW,
                          const int* __restrict__ parent, const int* __restrict__ kid,
                          float* __restrict__ cat, int n0) {
    int t = blockIdx.x * blockDim.x + threadIdx.x;
    if (t >= n0 * 64) return;
    int i = t / 64, c = t % 64;
    if (c < 32) {
        cat[t] = idt[(size_t)i * 32 + c];
    } else {
        const float* xr = x1 + (size_t)parent[i] * 64;
        const float* w = upW + (size_t)kid[i] * 64 * 32 + (c - 32);
        float a = 0.f;
#pragma unroll
        for (int ci = 0; ci < 64; ++ci) a += xr[ci] * w[ci * 32];
        cat[t] = a;
    }
}

__global__ void wsc_add(const float* __restrict__ h, const float* __restrict__ cat,
                        const float* __restrict__ Wsc, float* __restrict__ out, int n0) {
    int t = blockIdx.x * blockDim.x + threadIdx.x;
    if (t >= n0 * 32) return;
    int i = t / 32, c = t % 32;
    float a = h[t];
    const float* xr = cat + (size_t)i * 64;
#pragma unroll
    for (int ci = 0; ci < 64; ++ci) a += xr[ci] * Wsc[ci * 32 + c];
    out[t] = a;
}

// ---------------- host ----------------
static inline int ceil_div(int a, int b) { return (a + b - 1) / b; }
static inline int bf_smem(int cin, int cout, int K, int BR, bool db) {
    int pxb = cin / 2 + 4;
    int set = 4 * (2 * BR + 2 * cout) * pxb;
    return set * (db ? 2 : 1) + 2 * BR * K + 16;
}

extern "C" void kernel_launch(void* const* d_in, const int* in_sizes, int n_in,
                              void* d_out, int out_size) {
    const float* feats     = (const float*)d_in[0];
    const float* res0_W    = (const float*)d_in[1];
    const float* res0_bn   = (const float*)d_in[2];
    const float* down_bn   = (const float*)d_in[3];
    const float* down_W    = (const float*)d_in[4];
    const float* res1_W    = (const float*)d_in[5];
    const float* res1_bn   = (const float*)d_in[6];
    const float* up_bn     = (const float*)d_in[7];
    const float* up_W      = (const float*)d_in[8];
    const float* tail0_bn1 = (const float*)d_in[9];
    const float* tail0_W1  = (const float*)d_in[10];
    const float* tail0_bn2 = (const float*)d_in[11];
    const float* tail0_W2  = (const float*)d_in[12];
    const float* tail0_Wsc = (const float*)d_in[13];
    const float* tail1_W   = (const float*)d_in[14];
    const float* tail1_bn  = (const float*)d_in[15];
    const int* subm0_in    = (const int*)d_in[16];
    const int* subm0_out   = (const int*)d_in[17];
    const int* subm1_in    = (const int*)d_in[18];
    const int* subm1_out   = (const int*)d_in[19];
    const int* down_in     = (const int*)d_in[20];
    const int* down_out    = (const int*)d_in[21];
    const int* n1p         = (const int*)d_in[22];

    const int n0 = in_sizes[0] / 32;
    const int P0 = in_sizes[16] / 27;
    const int P1 = in_sizes[18] / 27;
    const int PD = in_sizes[20] / 8;

    float *f0a, *f0b, *f0c, *cat, *f1a, *f1b, *f1c;
    int *nbr0, *nbr1, *nbrD, *parent, *kid;
    uint16_t *wh, *wl;
    uint32_t *ph32, *pl32, *ph64, *pl64;
    cudaGetSymbolAddress((void**)&f0a, g_f0a);
    cudaGetSymbolAddress((void**)&f0b, g_f0b);
    cudaGetSymbolAddress((void**)&f0c, g_f0c);
    cudaGetSymbolAddress((void**)&cat, g_cat);
    cudaGetSymbolAddress((void**)&f1a, g_f1a);
    cudaGetSymbolAddress((void**)&f1b, g_f1b);
    cudaGetSymbolAddress((void**)&f1c, g_f1c);
    cudaGetSymbolAddress((void**)&nbr0, g_nbr0);
    cudaGetSymbolAddress((void**)&nbr1, g_nbr1);
    cudaGetSymbolAddress((void**)&nbrD, g_nbrD);
    cudaGetSymbolAddress((void**)&parent, g_parent);
    cudaGetSymbolAddress((void**)&kid, g_kid);
    cudaGetSymbolAddress((void**)&wh, g_wh);
    cudaGetSymbolAddress((void**)&wl, g_wl);
    cudaGetSymbolAddress((void**)&ph32, g_ph32);
    cudaGetSymbolAddress((void**)&pl32, g_pl32);
    cudaGetSymbolAddress((void**)&ph64, g_ph64);
    cudaGetSymbolAddress((void**)&pl64, g_pl64);

    const int S3232 = bf_smem(32, 32, 27, 128, true);
    const int S3264 = bf_smem(32, 64, 8, 128, true);
    const int S6464 = bf_smem(64, 64, 27, 64, false);
    const int S6432 = bf_smem(64, 32, 27, 128, false);
    cudaFuncSetAttribute((const void*)conv_bf<32, 32, 128, 1, true>,
                         cudaFuncAttributeMaxDynamicSharedMemorySize, S3232);
    cudaFuncSetAttribute((const void*)conv_bf<32, 64, 128, 1, true>,
                         cudaFuncAttributeMaxDynamicSharedMemorySize, S3264);
    cudaFuncSetAttribute((const void*)conv_bf<64, 64, 64, 2, false>,
                         cudaFuncAttributeMaxDynamicSharedMemorySize, S6464);
    cudaFuncSetAttribute((const void*)conv_bf<64, 32, 128, 1, false>,
                         cudaFuncAttributeMaxDynamicSharedMemorySize, S6432);

    const int TB = 256;
    const int G0 = ceil_div(n0, 128);
    const int G1_128 = ceil_div(N1MAX, 128);
    const int G1_64  = ceil_div(N1MAX, 64);
    const int E164 = (N1MAX + 1) * 64;
    const int PP0_32 = n0 * 16;             // pairs for level0 C32
    const int PP0_64 = n0 * 32;             // pairs for level0 C64 (cat)
    const int PP1_64 = N1MAX * 32;          // pairs for level1 C64

    // ---- setup ----
    fill_i32<<<ceil_div((N0 + 1) * 27, TB), TB>>>(nbr0, (N0 + 1) * 27, n0, nullptr);
    scatter_pairs<<<ceil_div(27 * P0, TB), TB>>>(subm0_in, subm0_out, 27 * P0, P0, 27, nbr0);
    wsplit_all<<<ceil_div(WTOTAL, TB), TB>>>(res0_W, tail0_W2, tail1_W, tail0_W1,
                                             down_W, res1_W, wh, wl);

    // ---- res0 blocks ----
    const float* x = feats;
    for (int rep = 0; rep < 2; ++rep) {
        prep_bf<32><<<ceil_div(PP0_32, TB), TB>>>(x, res0_bn + (rep * 2 + 0) * 128,
                                                  ph32, pl32, n0, nullptr, PP0_32);
        if (rep == 0)
            fill_i32<<<ceil_div((N1MAX + 1) * 27, TB), TB>>>(nbr1, (N1MAX + 1) * 27, 0, n1p);
        conv_bf<32, 32, 128, 1, true><<<G0, 256, S3232>>>(
            ph32, pl32, wh, wl, WOFF_RES0 + (rep * 2 + 0) * 27648,
            nbr0, 27, nullptr, f0c, n0, nullptr, n0, nullptr);
        prep_bf<32><<<ceil_div(PP0_32, TB), TB>>>(f0c, res0_bn + (rep * 2 + 1) * 128,
                                                  ph32, pl32, n0, nullptr, PP0_32);
        conv_bf<32, 32, 128, 1, true><<<G0, 256, S3232>>>(
            ph32, pl32, wh, wl, WOFF_RES0 + (rep * 2 + 1) * 27648,
            nbr0, 27, x, f0a, n0, nullptr, n0, nullptr);
        x = f0a;
    }
    // f0a = identity

    scatter_pairs<<<ceil_div(27 * P1, TB), TB>>>(subm1_in, subm1_out, 27 * P1, P1, 27, nbr1);
    fill_i32<<<ceil_div((N1MAX + 1) * 8, TB), TB>>>(nbrD, (N1MAX + 1) * 8, n0, nullptr);
    scatter_pairs<<<ceil_div(8 * PD, TB), TB>>>(down_in, down_out, 8 * PD, PD, 8, nbrD);
    fill_i32<<<ceil_div(N0 + 1, TB), TB>>>(parent, N0 + 1, 0, n1p);
    fill_i32<<<ceil_div(N0 + 1, TB), TB>>>(kid, N0 + 1, 0, nullptr);
    scatter_parent<<<ceil_div(8 * PD, TB), TB>>>(down_in, down_out, 8 * PD, PD, n0, parent, kid);

    // ---- down conv ----
    prep_bf<32><<<ceil_div(PP0_32, TB), TB>>>(f0a, down_bn, ph32, pl32, n0, nullptr, PP0_32);
    conv_bf<32, 64, 128, 1, true><<<G1_128, 256, S3264>>>(
        ph32, pl32, wh, wl, WOFF_DOWN, nbrD, 8, nullptr, f1a, 0, n1p, n0, nullptr);

    // ---- res1 blocks ----
    for (int rep = 0; rep < 2; ++rep) {
        prep_bf<64><<<ceil_div(PP1_64, TB), TB>>>(f1a, res1_bn + (rep * 2 + 0) * 256,
                                                  ph64, pl64, 0, n1p, PP1_64);
        conv_bf<64, 64, 64, 2, false><<<G1_64, 256, S6464>>>(
            ph64, pl64, wh, wl, WOFF_RES1 + (rep * 2 + 0) * 110592,
            nbr1, 27, nullptr, f1c, 0, n1p, 0, n1p);
        prep_bf<64><<<ceil_div(PP1_64, TB), TB>>>(f1c, res1_bn + (rep * 2 + 1) * 256,
                                                  ph64, pl64, 0, n1p, PP1_64);
        conv_bf<64, 64, 64, 2, false><<<G1_64, 256, S6464>>>(
            ph64, pl64, wh, wl, WOFF_RES1 + (rep * 2 + 1) * 110592,
            nbr1, 27, f1a, f1a, 0, n1p, 0, n1p);
    }

    // ---- up conv + concat ----
    bnrelu_k<64><<<ceil_div(E164, TB), TB>>>(f1a, up_bn, f1b, 0, n1p, E164);
    up_concat<<<ceil_div(n0 * 64, TB), TB>>>(f0a, f1b, up_W, parent, kid, cat, n0);

    // ---- tail0 ----
    prep_bf<64><<<ceil_div(PP0_64, TB), TB>>>(cat, tail0_bn1, ph64, pl64, n0, nullptr, PP0_64);
    conv_bf<64, 32, 128, 1, false><<<G0, 256, S6432>>>(
        ph64, pl64, wh, wl, WOFF_T0W1, nbr0, 27, nullptr, f0b, n0, nullptr, n0, nullptr);
    prep_bf<32><<<ceil_div(PP0_32, TB), TB>>>(f0b, tail0_bn2, ph32, pl32, n0, nullptr, PP0_32);
    conv_bf<32, 32, 128, 1, true><<<G0, 256, S3232>>>(
        ph32, pl32, wh, wl, WOFF_T0W2, nbr0, 27, nullptr, f0c, n0, nullptr, n0, nullptr);
    wsc_add<<<ceil_div(n0 * 32, TB), TB>>>(f0c, cat, tail0_Wsc, f0b, n0);

    // ---- tail1 res block -> d_out ----
    prep_bf<32><<<ceil_div(PP0_32, TB), TB>>>(f0b, tail1_bn + 0, ph32, pl32, n0, nullptr, PP0_32);
    conv_bf<32, 32, 128, 1, true><<<G0, 256, S3232>>>(
        ph32, pl32, wh, wl, WOFF_T1, nbr0, 27, nullptr, f0a, n0, nullptr, n0, nullptr);
    prep_bf<32><<<ceil_div(PP0_32, TB), TB>>>(f0a, tail1_bn + 128, ph32, pl32, n0, nullptr, PP0_32);
    conv_bf<32, 32, 128, 1, true><<<G0, 256, S3232>>>(
        ph32, pl32, wh, wl, WOFF_T1 + 27648, nbr0, 27,
        f0b, (float*)d_out, n0, nullptr, n0, nullptr);
}

// round 17
// speedup vs baseline: 2.8969x; 1.0632x over previous
#include <cuda_runtime.h>
#include <cuda_bf16.h>
#include <cstdint>

#define N0 48000
#define N1MAX 32000
#define EPSV 1e-4f

__device__ float g_f0a[(N0 + 1) * 32];
__device__ float g_f0b[(N0 + 1) * 32];
__device__ float g_f0c[(N0 + 1) * 32];
__device__ float g_cat[(N0 + 1) * 64];
__device__ float g_f1a[(N1MAX + 1) * 64];
__device__ float g_f1b[(N1MAX + 1) * 64];
__device__ float g_f1c[(N1MAX + 1) * 64];
__device__ int g_nbr0[(N0 + 1) * 27];
__device__ int g_nbr1[(N1MAX + 1) * 27];
__device__ int g_nbrD[(N1MAX + 1) * 8];
__device__ int g_parent[N0 + 1];
__device__ int g_kid[N0 + 1];
__device__ __align__(16) uint16_t g_wh[707584];
__device__ __align__(16) uint16_t g_wl[707584];
__device__ __align__(16) uint32_t g_ph32[(N0 + 1) * 16];
__device__ __align__(16) uint32_t g_pl32[(N0 + 1) * 16];
__device__ __align__(16) uint32_t g_ph64[(N0 + 1) * 32];
__device__ __align__(16) uint32_t g_pl64[(N0 + 1) * 32];

#define WOFF_RES0   0
#define WOFF_T0W2   110592
#define WOFF_T1     138240
#define WOFF_T0W1   193536
#define WOFF_DOWN   248832
#define WOFF_RES1   265216
#define WTOTAL      707584

// ---------------- helpers ----------------
__device__ __forceinline__ void bfsplit(float v, uint16_t& h, uint16_t& l) {
    __nv_bfloat16 hb = __float2bfloat16_rn(v);
    float r = v - __bfloat162float(hb);
    __nv_bfloat16 lb = __float2bfloat16_rn(r);
    h = *reinterpret_cast<uint16_t*>(&hb);
    l = *reinterpret_cast<uint16_t*>(&lb);
}
__device__ __forceinline__ uint32_t pk(uint16_t a, uint16_t b) {
    return (uint32_t)a | ((uint32_t)b << 16);
}
__device__ __forceinline__ void mma16(float4& d, const uint32_t* a, const uint32_t* b) {
    asm volatile(
        "mma.sync.aligned.m16n8k16.row.col.f32.bf16.bf16.f32 "
        "{%0,%1,%2,%3}, {%4,%5,%6,%7}, {%8,%9}, {%0,%1,%2,%3};"
        : "+f"(d.x), "+f"(d.y), "+f"(d.z), "+f"(d.w)
        : "r"(a[0]), "r"(a[1]), "r"(a[2]), "r"(a[3]), "r"(b[0]), "r"(b[1]));
}
__device__ __forceinline__ uint32_t sptr(const void* p) {
    return (uint32_t)__cvta_generic_to_shared(p);
}
#define CPA16(dst, src, sz) \
    asm volatile("cp.async.ca.shared.global [%0], [%1], 16, %2;" \
                 :: "r"(dst), "l"(src), "r"(sz) : "memory")
#define CPA_COMMIT() asm volatile("cp.async.commit_group;" ::: "memory")
#define CPA_WAIT0()  asm volatile("cp.async.wait_group 0;" ::: "memory")

// ---------------- setup kernels ----------------
__global__ void fill_i32(int* p, int count, int val, const int* vptr) {
    int t = blockIdx.x * blockDim.x + threadIdx.x;
    if (t >= count) return;
    p[t] = vptr ? *vptr : val;
}

__global__ void scatter_pairs(const int* __restrict__ pin, const int* __restrict__ pout,
                              int total, int P, int K, int* __restrict__ nbr) {
    int t = blockIdx.x * blockDim.x + threadIdx.x;
    if (t >= total) return;
    int k = t / P;
    nbr[pout[t] * K + k] = pin[t];
}

__global__ void scatter_parent(const int* __restrict__ din, const int* __restrict__ dout,
                               int total, int P, int n0,
                               int* __restrict__ parent, int* __restrict__ kid) {
    int t = blockIdx.x * blockDim.x + threadIdx.x;
    if (t >= total) return;
    int k = t / P;
    int i = din[t];
    if (i < n0) { parent[i] = dout[t]; kid[i] = k; }
}

__global__ void wsplit_all(const float* __restrict__ res0, const float* __restrict__ t0w2,
                           const float* __restrict__ t1w, const float* __restrict__ t0w1,
                           const float* __restrict__ dW, const float* __restrict__ r1w,
                           uint16_t* __restrict__ wh, uint16_t* __restrict__ wl) {
    int e = blockIdx.x * blockDim.x + threadIdx.x;
    if (e >= WTOTAL) return;
    const float* src;
    int base, cin, cout;
    if (e < WOFF_T0W2)      { src = res0; base = WOFF_RES0; cin = 32; cout = 32; }
    else if (e < WOFF_T0W1) {
        if (e < WOFF_T1) { src = t0w2; base = WOFF_T0W2; }
        else             { src = t1w;  base = WOFF_T1; }
        cin = 32; cout = 32;
    }
    else if (e < WOFF_DOWN) { src = t0w1; base = WOFF_T0W1; cin = 64; cout = 32; }
    else if (e < WOFF_RES1) { src = dW;   base = WOFF_DOWN; cin = 32; cout = 64; }
    else                    { src = r1w;  base = WOFF_RES1; cin = 64; cout = 64; }
    int rel = e - base, tc = cin * cout;
    int tap = rel / tc, r = rel % tc, k = r / cout, n = r % cout;
    float w = src[rel];
    uint16_t h, l;
    bfsplit(w, h, l);
    int dst = base + tap * tc + n * cin + k;
    wh[dst] = h;
    wl[dst] = l;
}

// bnrelu + bf16 hi/lo split, packed pairs: one pass per conv input
template <int C>
__global__ void prep_bf(const float* __restrict__ x, const float* __restrict__ bn,
                        uint32_t* __restrict__ ph, uint32_t* __restrict__ pl,
                        int n_host, const int* __restrict__ n_dev, int total_pairs) {
    int t = blockIdx.x * blockDim.x + threadIdx.x;
    if (t >= total_pairs) return;
    int n = n_dev ? *n_dev : n_host;
    int r = t / (C / 2), j = t % (C / 2);
    uint32_t hw = 0, lw = 0;
    if (r < n) {
        int c0 = 2 * j, c1 = 2 * j + 1;
        float s0 = bn[c0] * rsqrtf(bn[3 * C + c0] + EPSV);
        float s1 = bn[c1] * rsqrtf(bn[3 * C + c1] + EPSV);
        float b0 = bn[C + c0] - bn[2 * C + c0] * s0;
        float b1 = bn[C + c1] - bn[2 * C + c1] * s1;
        float2 v = *(const float2*)(x + (size_t)r * C + c0);
        v.x = fmaxf(fmaf(v.x, s0, b0), 0.f);
        v.y = fmaxf(fmaf(v.y, s1, b1), 0.f);
        uint16_t h0, l0, h1, l1;
        bfsplit(v.x, h0, l0);
        bfsplit(v.y, h1, l1);
        hw = pk(h0, h1);
        lw = pk(l0, l1);
    }
    ph[t] = hw;
    pl[t] = lw;
}

// ---------------- async staging of one tap tile ----------
template <int CIN, int COUT, int BR, int NT>
__device__ __forceinline__ void stage_async(
    const uint32_t* __restrict__ xh, const uint32_t* __restrict__ xl,
    const uint16_t* __restrict__ whG, const uint16_t* __restrict__ wlG,
    const unsigned short* __restrict__ idxAll, int K, int k, int nin,
    uint32_t sXh, uint32_t sXl, uint32_t sWh, uint32_t sWl, int tid) {
    constexpr int PXB = CIN / 2 + 4;
#pragma unroll 1
    for (int e = tid; e < BR * (CIN / 8); e += NT) {
        int r = e / (CIN / 8), seg = e % (CIN / 8);
        int idx = idxAll[r * K + k];
        int ok = (idx < nin) ? 16 : 0;
        int s = (idx < nin) ? idx : 0;
        uint32_t d = (uint32_t)(r * PXB + seg * 4) * 4u;
        CPA16(sXh + d, xh + (size_t)s * (CIN / 2) + seg * 4, ok);
        CPA16(sXl + d, xl + (size_t)s * (CIN / 2) + seg * 4, ok);
    }
    const uint16_t* wh = whG + (size_t)k * CIN * COUT;
    const uint16_t* wl = wlG + (size_t)k * CIN * COUT;
#pragma unroll 1
    for (int e = tid; e < COUT * (CIN / 8); e += NT) {
        int nr = e / (CIN / 8), seg = e % (CIN / 8);
        uint32_t d = (uint32_t)(nr * PXB + seg * 4) * 4u;
        CPA16(sWh + d, wh + nr * CIN + seg * 8, 16);
        CPA16(sWl + d, wl + nr * CIN + seg * 8, 16);
    }
}

// ---------------- bf16x3 mma.sync gather implicit-GEMM sparse conv --------
// cp.async double-buffered pipeline, one barrier per tap.
template <int CIN, int COUT, int BR, int CW>
__global__ void __launch_bounds__((BR / 16) * CW * 32)
conv_bf(const uint32_t* __restrict__ xh, const uint32_t* __restrict__ xl,
        const uint16_t* __restrict__ whG, const uint16_t* __restrict__ wlG, int woff,
        const int* __restrict__ nbr, int K,
        const float* __restrict__ res, float* __restrict__ out,
        int nout_h, const int* __restrict__ nout_d,
        int nin_h, const int* __restrict__ nin_d) {
    constexpr int PXB = CIN / 2 + 4;
    constexpr int NT = (BR / 16) * CW * 32;
    constexpr int KC = CIN / 16;
    constexpr int CPW = COUT / CW;
    constexpr int NTILE = CPW / 8;
    constexpr int SET = (2 * BR + 2 * COUT) * PXB;   // u32 words per buffer
    extern __shared__ uint32_t smem[];
    unsigned short* idxAll = (unsigned short*)(smem + 2 * SET);

    int n = nout_d ? *nout_d : nout_h;
    int nin = nin_d ? *nin_d : nin_h;
    int row0 = blockIdx.x * BR;
    if (row0 >= n) return;
    int tid = threadIdx.x, wid = tid >> 5, lane = tid & 31;
    int grp = lane >> 2, tg = lane & 3;
    int rw = wid / CW, cw = wid % CW;
    int mrow = rw * 16, colbase = cw * CPW;

    for (int e = tid; e < BR * K; e += NT)
        idxAll[e] = (unsigned short)((row0 + e / K < n) ? nbr[(size_t)row0 * K + e] : nin);
    __syncthreads();

    const uint16_t* whB = whG + woff;
    const uint16_t* wlB = wlG + woff;
    const uint32_t sb = sptr(smem);
    auto sX = [&](int b) { return sb + (uint32_t)(b * SET) * 4u; };

    float4 acc[NTILE];
#pragma unroll
    for (int i = 0; i < NTILE; ++i) acc[i] = make_float4(0.f, 0.f, 0.f, 0.f);

    auto compute = [&](const uint32_t* buf) {
        const uint32_t* Xh = buf;
        const uint32_t* Xl = buf + BR * PXB;
        const uint32_t* Wh = buf + 2 * BR * PXB;
        const uint32_t* Wl = Wh + COUT * PXB;
#pragma unroll
        for (int kc = 0; kc < KC; ++kc) {
            int c0 = kc * 8 + tg;
            uint32_t ah[4], al[4];
            ah[0] = Xh[(mrow + grp) * PXB + c0];
            ah[1] = Xh[(mrow + grp + 8) * PXB + c0];
            ah[2] = Xh[(mrow + grp) * PXB + c0 + 4];
            ah[3] = Xh[(mrow + grp + 8) * PXB + c0 + 4];
            al[0] = Xl[(mrow + grp) * PXB + c0];
            al[1] = Xl[(mrow + grp + 8) * PXB + c0];
            al[2] = Xl[(mrow + grp) * PXB + c0 + 4];
            al[3] = Xl[(mrow + grp + 8) * PXB + c0 + 4];
#pragma unroll
            for (int nt = 0; nt < NTILE; ++nt) {
                int nb = colbase + nt * 8 + grp;
                uint32_t bh[2] = {Wh[nb * PXB + c0], Wh[nb * PXB + c0 + 4]};
                uint32_t bl[2] = {Wl[nb * PXB + c0], Wl[nb * PXB + c0 + 4]};
                mma16(acc[nt], ah, bh);
                mma16(acc[nt], ah, bl);
                mma16(acc[nt], al, bh);
            }
        }
    };

    // pipeline: stage(0); per tap: wait -> barrier -> stage(k+1) -> compute(k)
    {
        uint32_t b0 = sX(0);
        stage_async<CIN, COUT, BR, NT>(xh, xl, whB, wlB, idxAll, K, 0, nin,
                                       b0, b0 + BR * PXB * 4, b0 + 2 * BR * PXB * 4,
                                       b0 + (2 * BR + COUT) * PXB * 4, tid);
        CPA_COMMIT();
    }
    for (int k = 0; k < K; ++k) {
        CPA_WAIT0();
        __syncthreads();   // data(k) visible; all warps done compute(k-1)
        if (k + 1 < K) {
            uint32_t ba = sX((k + 1) & 1);
            stage_async<CIN, COUT, BR, NT>(xh, xl, whB, wlB, idxAll, K, k + 1, nin,
                                           ba, ba + BR * PXB * 4, ba + 2 * BR * PXB * 4,
                                           ba + (2 * BR + COUT) * PXB * 4, tid);
            CPA_COMMIT();
        }
        compute(smem + (k & 1) * SET);
    }

    int r0 = row0 + mrow + grp;
    int r1 = r0 + 8;
#pragma unroll
    for (int nt = 0; nt < NTILE; ++nt) {
        int c = colbase + nt * 8 + 2 * tg;
        if (r0 < n) {
            float2 v = make_float2(acc[nt].x, acc[nt].y);
            if (res) {
                float2 rv = *(const float2*)(res + (size_t)r0 * COUT + c);
                v.x += rv.x; v.y += rv.y;
            }
            *(float2*)(out + (size_t)r0 * COUT + c) = v;
        }
        if (r1 < n) {
            float2 v = make_float2(acc[nt].z, acc[nt].w);
            if (res) {
                float2 rv = *(const float2*)(res + (size_t)r1 * COUT + c);
                v.x += rv.x; v.y += rv.y;
            }
            *(float2*)(out + (size_t)r1 * COUT + c) = v;
        }
    }
}

template <int C>
__global__ void bnrelu_k(const float* __restrict__ x, const float* __restrict__ bn,
                         float* __restrict__ y, int n_host, const int* __restrict__ n_dev,
                         int total) {
    int t = blockIdx.x * blockDim.x + threadIdx.x;
    if (t >= total) return;
    int n = n_dev ? *n_dev : n_host;
    int r = t / C, c = t % C;
    float v = 0.f;
    if (r < n) {
        float g = bn[c], be = bn[C + c], m = bn[2 * C + c], va = bn[3 * C + c];
        v = fmaxf((x[t] - m) * (g * rsqrtf(va + EPSV)) + be, 0.f);
    }
    y[t] = v;
}

__global__ void up_concat(const float* __restrict__ idt, const float* __restrict__ x1,
                          const float* __restrict__ upW,
                          const int* __restrict__ parent, const int* __restrict__ kid,
                          float* __restrict__ cat, int n0) {
    int t = blockIdx.x * blockDim.x + threadIdx.x;
    if (t >= n0 * 64) return;
    int i = t / 64, c = t % 64;
    if (c < 32) {
        cat[t] = idt[(size_t)i * 32 + c];
    } else {
        const float* xr = x1 + (size_t)parent[i] * 64;
        const float* w = upW + (size_t)kid[i] * 64 * 32 + (c - 32);
        float a = 0.f;
#pragma unroll
        for (int ci = 0; ci < 64; ++ci) a += xr[ci] * w[ci * 32];
        cat[t] = a;
    }
}

__global__ void wsc_add(const float* __restrict__ h, const float* __restrict__ cat,
                        const float* __restrict__ Wsc, float* __restrict__ out, int n0) {
    int t = blockIdx.x * blockDim.x + threadIdx.x;
    if (t >= n0 * 32) return;
    int i = t / 32, c = t % 32;
    float a = h[t];
    const float* xr = cat + (size_t)i * 64;
#pragma unroll
    for (int ci = 0; ci < 64; ++ci) a += xr[ci] * Wsc[ci * 32 + c];
    out[t] = a;
}

// ---------------- host ----------------
static inline int ceil_div(int a, int b) { return (a + b - 1) / b; }
static inline int bf_smem(int cin, int cout, int K, int BR) {
    int pxb = cin / 2 + 4;
    int set = 4 * (2 * BR + 2 * cout) * pxb;
    return 2 * set + 2 * BR * K + 16;
}

extern "C" void kernel_launch(void* const* d_in, const int* in_sizes, int n_in,
                              void* d_out, int out_size) {
    const float* feats     = (const float*)d_in[0];
    const float* res0_W    = (const float*)d_in[1];
    const float* res0_bn   = (const float*)d_in[2];
    const float* down_bn   = (const float*)d_in[3];
    const float* down_W    = (const float*)d_in[4];
    const float* res1_W    = (const float*)d_in[5];
    const float* res1_bn   = (const float*)d_in[6];
    const float* up_bn     = (const float*)d_in[7];
    const float* up_W      = (const float*)d_in[8];
    const float* tail0_bn1 = (const float*)d_in[9];
    const float* tail0_W1  = (const float*)d_in[10];
    const float* tail0_bn2 = (const float*)d_in[11];
    const float* tail0_W2  = (const float*)d_in[12];
    const float* tail0_Wsc = (const float*)d_in[13];
    const float* tail1_W   = (const float*)d_in[14];
    const float* tail1_bn  = (const float*)d_in[15];
    const int* subm0_in    = (const int*)d_in[16];
    const int* subm0_out   = (const int*)d_in[17];
    const int* subm1_in    = (const int*)d_in[18];
    const int* subm1_out   = (const int*)d_in[19];
    const int* down_in     = (const int*)d_in[20];
    const int* down_out    = (const int*)d_in[21];
    const int* n1p         = (const int*)d_in[22];

    const int n0 = in_sizes[0] / 32;
    const int P0 = in_sizes[16] / 27;
    const int P1 = in_sizes[18] / 27;
    const int PD = in_sizes[20] / 8;

    float *f0a, *f0b, *f0c, *cat, *f1a, *f1b, *f1c;
    int *nbr0, *nbr1, *nbrD, *parent, *kid;
    uint16_t *wh, *wl;
    uint32_t *ph32, *pl32, *ph64, *pl64;
    cudaGetSymbolAddress((void**)&f0a, g_f0a);
    cudaGetSymbolAddress((void**)&f0b, g_f0b);
    cudaGetSymbolAddress((void**)&f0c, g_f0c);
    cudaGetSymbolAddress((void**)&cat, g_cat);
    cudaGetSymbolAddress((void**)&f1a, g_f1a);
    cudaGetSymbolAddress((void**)&f1b, g_f1b);
    cudaGetSymbolAddress((void**)&f1c, g_f1c);
    cudaGetSymbolAddress((void**)&nbr0, g_nbr0);
    cudaGetSymbolAddress((void**)&nbr1, g_nbr1);
    cudaGetSymbolAddress((void**)&nbrD, g_nbrD);
    cudaGetSymbolAddress((void**)&parent, g_parent);
    cudaGetSymbolAddress((void**)&kid, g_kid);
    cudaGetSymbolAddress((void**)&wh, g_wh);
    cudaGetSymbolAddress((void**)&wl, g_wl);
    cudaGetSymbolAddress((void**)&ph32, g_ph32);
    cudaGetSymbolAddress((void**)&pl32, g_pl32);
    cudaGetSymbolAddress((void**)&ph64, g_ph64);
    cudaGetSymbolAddress((void**)&pl64, g_pl64);

    const int S3232 = bf_smem(32, 32, 27, 128);
    const int S3264 = bf_smem(32, 64, 8, 128);
    const int S6464 = bf_smem(64, 64, 27, 64);
    const int S6432 = bf_smem(64, 32, 27, 64);
    cudaFuncSetAttribute((const void*)conv_bf<32, 32, 128, 1>,
                         cudaFuncAttributeMaxDynamicSharedMemorySize, S3232);
    cudaFuncSetAttribute((const void*)conv_bf<32, 64, 128, 1>,
                         cudaFuncAttributeMaxDynamicSharedMemorySize, S3264);
    cudaFuncSetAttribute((const void*)conv_bf<64, 64, 64, 2>,
                         cudaFuncAttributeMaxDynamicSharedMemorySize, S6464);
    cudaFuncSetAttribute((const void*)conv_bf<64, 32, 64, 2>,
                         cudaFuncAttributeMaxDynamicSharedMemorySize, S6432);

    const int TB = 256;
    const int G0 = ceil_div(n0, 128);
    const int G0_64 = ceil_div(n0, 64);
    const int G1_128 = ceil_div(N1MAX, 128);
    const int G1_64 = ceil_div(N1MAX, 64);
    const int E164 = (N1MAX + 1) * 64;
    const int PP0_32 = n0 * 16;
    const int PP0_64 = n0 * 32;
    const int PP1_64 = N1MAX * 32;

    // ---- setup ----
    fill_i32<<<ceil_div((N0 + 1) * 27, TB), TB>>>(nbr0, (N0 + 1) * 27, n0, nullptr);
    scatter_pairs<<<ceil_div(27 * P0, TB), TB>>>(subm0_in, subm0_out, 27 * P0, P0, 27, nbr0);
    wsplit_all<<<ceil_div(WTOTAL, TB), TB>>>(res0_W, tail0_W2, tail1_W, tail0_W1,
                                             down_W, res1_W, wh, wl);

    // ---- res0 blocks ----
    const float* x = feats;
    for (int rep = 0; rep < 2; ++rep) {
        prep_bf<32><<<ceil_div(PP0_32, TB), TB>>>(x, res0_bn + (rep * 2 + 0) * 128,
                                                  ph32, pl32, n0, nullptr, PP0_32);
        if (rep == 0)
            fill_i32<<<ceil_div((N1MAX + 1) * 27, TB), TB>>>(nbr1, (N1MAX + 1) * 27, 0, n1p);
        conv_bf<32, 32, 128, 1><<<G0, 256, S3232>>>(
            ph32, pl32, wh, wl, WOFF_RES0 + (rep * 2 + 0) * 27648,
            nbr0, 27, nullptr, f0c, n0, nullptr, n0, nullptr);
        prep_bf<32><<<ceil_div(PP0_32, TB), TB>>>(f0c, res0_bn + (rep * 2 + 1) * 128,
                                                  ph32, pl32, n0, nullptr, PP0_32);
        conv_bf<32, 32, 128, 1><<<G0, 256, S3232>>>(
            ph32, pl32, wh, wl, WOFF_RES0 + (rep * 2 + 1) * 27648,
            nbr0, 27, x, f0a, n0, nullptr, n0, nullptr);
        x = f0a;
    }
    // f0a = identity

    scatter_pairs<<<ceil_div(27 * P1, TB), TB>>>(subm1_in, subm1_out, 27 * P1, P1, 27, nbr1);
    fill_i32<<<ceil_div((N1MAX + 1) * 8, TB), TB>>>(nbrD, (N1MAX + 1) * 8, n0, nullptr);
    scatter_pairs<<<ceil_div(8 * PD, TB), TB>>>(down_in, down_out, 8 * PD, PD, 8, nbrD);
    fill_i32<<<ceil_div(N0 + 1, TB), TB>>>(parent, N0 + 1, 0, n1p);
    fill_i32<<<ceil_div(N0 + 1, TB), TB>>>(kid, N0 + 1, 0, nullptr);
    scatter_parent<<<ceil_div(8 * PD, TB), TB>>>(down_in, down_out, 8 * PD, PD, n0, parent, kid);

    // ---- down conv ----
    prep_bf<32><<<ceil_div(PP0_32, TB), TB>>>(f0a, down_bn, ph32, pl32, n0, nullptr, PP0_32);
    conv_bf<32, 64, 128, 1><<<G1_128, 256, S3264>>>(
        ph32, pl32, wh, wl, WOFF_DOWN, nbrD, 8, nullptr, f1a, 0, n1p, n0, nullptr);

    // ---- res1 blocks ----
    for (int rep = 0; rep < 2; ++rep) {
        prep_bf<64><<<ceil_div(PP1_64, TB), TB>>>(f1a, res1_bn + (rep * 2 + 0) * 256,
                                                  ph64, pl64, 0, n1p, PP1_64);
        conv_bf<64, 64, 64, 2><<<G1_64, 256, S6464>>>(
            ph64, pl64, wh, wl, WOFF_RES1 + (rep * 2 + 0) * 110592,
            nbr1, 27, nullptr, f1c, 0, n1p, 0, n1p);
        prep_bf<64><<<ceil_div(PP1_64, TB), TB>>>(f1c, res1_bn + (rep * 2 + 1) * 256,
                                                  ph64, pl64, 0, n1p, PP1_64);
        conv_bf<64, 64, 64, 2><<<G1_64, 256, S6464>>>(
            ph64, pl64, wh, wl, WOFF_RES1 + (rep * 2 + 1) * 110592,
            nbr1, 27, f1a, f1a, 0, n1p, 0, n1p);
    }

    // ---- up conv + concat ----
    bnrelu_k<64><<<ceil_div(E164, TB), TB>>>(f1a, up_bn, f1b, 0, n1p, E164);
    up_concat<<<ceil_div(n0 * 64, TB), TB>>>(f0a, f1b, up_W, parent, kid, cat, n0);

    // ---- tail0 ----
    prep_bf<64><<<ceil_div(PP0_64, TB), TB>>>(cat, tail0_bn1, ph64, pl64, n0, nullptr, PP0_64);
    conv_bf<64, 32, 64, 2><<<G0_64, 256, S6432>>>(
        ph64, pl64, wh, wl, WOFF_T0W1, nbr0, 27, nullptr, f0b, n0, nullptr, n0, nullptr);
    prep_bf<32><<<ceil_div(PP0_32, TB), TB>>>(f0b, tail0_bn2, ph32, pl32, n0, nullptr, PP0_32);
    conv_bf<32, 32, 128, 1><<<G0, 256, S3232>>>(
        ph32, pl32, wh, wl, WOFF_T0W2, nbr0, 27, nullptr, f0c, n0, nullptr, n0, nullptr);
    wsc_add<<<ceil_div(n0 * 32, TB), TB>>>(f0c, cat, tail0_Wsc, f0b, n0);

    // ---- tail1 res block -> d_out ----
    prep_bf<32><<<ceil_div(PP0_32, TB), TB>>>(f0b, tail1_bn + 0, ph32, pl32, n0, nullptr, PP0_32);
    conv_bf<32, 32, 128, 1><<<G0, 256, S3232>>>(
        ph32, pl32, wh, wl, WOFF_T1, nbr0, 27, nullptr, f0a, n0, nullptr, n0, nullptr);
    prep_bf<32><<<ceil_div(PP0_32, TB), TB>>>(f0a, tail1_bn + 128, ph32, pl32, n0, nullptr, PP0_32);
    conv_bf<32, 32, 128, 1><<<G0, 256, S3232>>>(
        ph32, pl32, wh, wl, WOFF_T1 + 27648, nbr0, 27,
        f0b, (float*)d_out, n0, nullptr, n0, nullptr);
}